// round 15
// baseline (speedup 1.0000x reference)
#include <cuda_runtime.h>
#include <cuda_bf16.h>
#include <math.h>
#include <stdint.h>

#define B_   4
#define H_   8
#define L_   4096
#define D_   64
#define DM_  512
#define NS_  27
#define BH_  (B_*H_)
#define BL_  (B_*L_)
#define NCH  8
#define CH   (L_/NCH)   // 512
#define SLOTS 216
#define CKOFF ((size_t)B_*SLOTS*DM_)

// ---------------- scratch (device globals; no runtime alloc) ----------------
__device__ float g_Q[BH_*L_*D_];
__device__ float g_Q1[BH_*L_*D_];
__device__ float g_K[BH_*L_*D_];
__device__ float g_V[BH_*L_*D_];
__device__ float g_M[BH_*L_];
__device__ float g_outtop[BH_*NS_*D_];
__device__ float g_meanV[BH_*D_];
__device__ float g_vpart[BH_*NCH*D_];
__device__ float g_attM[BH_*NCH*NS_];
__device__ float g_attS[BH_*NCH*NS_];
__device__ float g_attO[BH_*NCH*NS_*D_];
__device__ float g_base0[B_*DM_];
__device__ float g_base1[B_*DM_];
__device__ float g_basekv[2*B_*DM_];
__device__ float g_basep[B_*8*DM_];
__device__ float g_basep2[2*B_*8*DM_];
__device__ float g_Tkv[2*DM_*DM_];
__device__ float g_ck[2*B_*SLOTS*DM_];     // [0]=K corrections, [CKOFF]=V corrections
__device__ int   g_map[B_*L_];
__device__ int   g_cnt[B_];
__device__ int   g_idxA[L_*NS_];
__device__ int   g_idxB[L_*NS_];
__device__ int   g_topidx[BH_*NS_];

// bf16-split operand buffers
__device__ __nv_bfloat16 g_Axd_hi[(size_t)BL_*DM_];
__device__ __nv_bfloat16 g_Axd_lo[(size_t)BL_*DM_];
__device__ __nv_bfloat16 g_Axp_hi[(size_t)BL_*DM_];
__device__ __nv_bfloat16 g_Axp_lo[(size_t)BL_*DM_];
__device__ __nv_bfloat16 g_Wt_hi[4*DM_*DM_];   // w0q, w0k, w0v, w1q
__device__ __nv_bfloat16 g_Wt_lo[4*DM_*DM_];

// ---------------- Threefry-2x32 (JAX-exact) ----------------
__host__ __device__ __forceinline__ void tf2x32(unsigned k0, unsigned k1,
                                                unsigned x0, unsigned x1,
                                                unsigned* o0, unsigned* o1) {
    unsigned ks0 = k0, ks1 = k1, ks2 = 0x1BD11BDAu ^ k0 ^ k1;
    x0 += ks0; x1 += ks1;
#define TF_RND(r) { x0 += x1; x1 = (x1 << (r)) | (x1 >> (32 - (r))); x1 ^= x0; }
    TF_RND(13) TF_RND(15) TF_RND(26) TF_RND(6)   x0 += ks1; x1 += ks2 + 1u;
    TF_RND(17) TF_RND(29) TF_RND(16) TF_RND(24)  x0 += ks2; x1 += ks0 + 2u;
    TF_RND(13) TF_RND(15) TF_RND(26) TF_RND(6)   x0 += ks0; x1 += ks1 + 3u;
    TF_RND(17) TF_RND(29) TF_RND(16) TF_RND(24)  x0 += ks1; x1 += ks2 + 4u;
    TF_RND(13) TF_RND(15) TF_RND(26) TF_RND(6)   x0 += ks2; x1 += ks0 + 5u;
#undef TF_RND
    *o0 = x0; *o1 = x1;
}

struct IdxKeys { unsigned k0[2], k1[2]; int* out[2]; };
__global__ void idx2_kernel(IdxKeys ik) {
    int i = blockIdx.x * blockDim.x + threadIdx.x;
    if (i >= L_*NS_) return;
    int z = blockIdx.y;
    unsigned o0, o1;
    tf2x32(ik.k0[z], ik.k1[z], 0u, (unsigned)i, &o0, &o1);
    ik.out[z][i] = (int)((o0 ^ o1) & 4095u);
}

// ---------------- bf16-split conversion (MLP=4, both inputs one launch) ----
struct Cvt2 { const float4* src[2]; __nv_bfloat162* hi[2]; __nv_bfloat162* lo[2]; };
__global__ __launch_bounds__(256)
void cvt_pair2_kernel(Cvt2 c, int n4q) {   // n4q = N4/4
    int z = blockIdx.y;
    int i = blockIdx.x * 256 + threadIdx.x;
    if (i >= n4q) return;
    const float4* __restrict__ src = c.src[z];
    __nv_bfloat162* __restrict__ hi = c.hi[z];
    __nv_bfloat162* __restrict__ lo = c.lo[z];
    float4 v[4];
#pragma unroll
    for (int j = 0; j < 4; j++) v[j] = src[i + j * n4q];
#pragma unroll
    for (int j = 0; j < 4; j++) {
        int ii = i + j * n4q;
        float4 w = v[j];
        __nv_bfloat16 h0 = __float2bfloat16(w.x), h1 = __float2bfloat16(w.y);
        __nv_bfloat16 h2 = __float2bfloat16(w.z), h3 = __float2bfloat16(w.w);
        __nv_bfloat16 l0 = __float2bfloat16(w.x - __bfloat162float(h0));
        __nv_bfloat16 l1 = __float2bfloat16(w.y - __bfloat162float(h1));
        __nv_bfloat16 l2 = __float2bfloat16(w.z - __bfloat162float(h2));
        __nv_bfloat16 l3 = __float2bfloat16(w.w - __bfloat162float(h3));
        hi[ii*2]   = __nv_bfloat162(h0, h1);
        hi[ii*2+1] = __nv_bfloat162(h2, h3);
        lo[ii*2]   = __nv_bfloat162(l0, l1);
        lo[ii*2+1] = __nv_bfloat162(l2, l3);
    }
}

struct W4 { const float* w[4]; };
__global__ __launch_bounds__(1024)
void wt_cvt_all_kernel(W4 ws, __nv_bfloat16* __restrict__ hi, __nv_bfloat16* __restrict__ lo) {
    __shared__ float t[32][33];
    int tx = threadIdx.x, ty = threadIdx.y;
    int n0 = blockIdx.x * 32, k0 = blockIdx.y * 32;
    int z = blockIdx.z;
    const float* W = ws.w[z];
    size_t off = (size_t)z * DM_ * DM_;
    t[ty][tx] = W[(size_t)(k0 + ty) * DM_ + n0 + tx];
    __syncthreads();
    float v = t[tx][ty];
    int n = n0 + ty, k = k0 + tx;
    __nv_bfloat16 h = __float2bfloat16(v);
    hi[off + (size_t)n * DM_ + k] = h;
    lo[off + (size_t)n * DM_ + k] = __float2bfloat16(v - __bfloat162float(h));
}

// ---------------- PTX helpers ----------------
__device__ __forceinline__ void cp16s(uint32_t saddr, const void* g) {
    asm volatile("cp.async.cg.shared.global [%0], [%1], 16;\n" :: "r"(saddr), "l"(g));
}
#define CP_COMMIT() asm volatile("cp.async.commit_group;\n" ::: "memory")
#define CP_WAIT(n)  asm volatile("cp.async.wait_group %0;\n" :: "n"(n) : "memory")

__device__ __forceinline__ void ldsm4(uint32_t& r0, uint32_t& r1, uint32_t& r2, uint32_t& r3,
                                      uint32_t saddr) {
    asm volatile("ldmatrix.sync.aligned.m8n8.x4.shared.b16 {%0,%1,%2,%3}, [%4];"
                 : "=r"(r0), "=r"(r1), "=r"(r2), "=r"(r3) : "r"(saddr));
}

__device__ __forceinline__ void mma_bf16(float* c, const uint32_t* a, const uint32_t* b) {
    asm volatile("mma.sync.aligned.m16n8k16.row.col.f32.bf16.bf16.f32 "
                 "{%0,%1,%2,%3}, {%4,%5,%6,%7}, {%8,%9}, {%0,%1,%2,%3};"
                 : "+f"(c[0]), "+f"(c[1]), "+f"(c[2]), "+f"(c[3])
                 : "r"(a[0]), "r"(a[1]), "r"(a[2]), "r"(a[3]), "r"(b[0]), "r"(b[1]));
}

// ---------------- mma.sync bf16-split GEMM (BK=32, 2-stage, 2 CTAs/SM) -----
#define GST    40960
#define GSMEM  (2048 + 2*GST)

struct GJob { const __nv_bfloat16 *ahi, *alo, *bhi, *blo; const float* bias; float* c; };
struct G4 { GJob j[4]; };

__global__ __launch_bounds__(256, 2)
void gemm_mma4(G4 g4) {
    extern __shared__ char smem[];
    const uint32_t sb = (uint32_t)__cvta_generic_to_shared(smem);
    const int tid = threadIdx.x;
    const int lane = tid & 31, wid = tid >> 5;
    const int warpM = wid >> 2, warpN = wid & 3;
    const int row0 = blockIdx.y * 128, col0 = blockIdx.x * 128;
    GJob jb = g4.j[blockIdx.z];
    const __nv_bfloat16* __restrict__ Ahi = jb.ahi;
    const __nv_bfloat16* __restrict__ Alo = jb.alo;
    const __nv_bfloat16* __restrict__ Bhi = jb.bhi;
    const __nv_bfloat16* __restrict__ Blo = jb.blo;

    float* sbias = (float*)smem;
    if (tid < 128) sbias[tid] = jb.bias[col0 + tid];

    float acc[4][4][4];
#pragma unroll
    for (int i = 0; i < 4; i++)
#pragma unroll
        for (int j = 0; j < 4; j++)
#pragma unroll
            for (int r = 0; r < 4; r++) acc[i][j][r] = 0.f;

    const int a_row = warpM * 64 + (lane & 15);
    const int a_kb  = ((lane >> 4) * 8) * 2;
    const int b_row = warpN * 32 + (lane & 7) + ((lane >> 4) & 1) * 8;
    const int b_kb  = (((lane >> 3) & 1) * 8) * 2;

#define LOAD_CHUNK(c, s) {                                                     \
    uint32_t stb = sb + 2048 + (uint32_t)(s) * GST;                            \
    int k0 = (c) * 32;                                                         \
    _Pragma("unroll")                                                          \
    for (int j = 0; j < 8; j++) {                                              \
        int idx = tid + j * 256;                                               \
        int tile = idx >> 9, w = idx & 511;                                    \
        int r = w >> 2, cc = w & 3;                                            \
        uint32_t so = stb + (uint32_t)tile * 10240u + (uint32_t)(r * 80 + cc * 16); \
        const __nv_bfloat16* gp;                                               \
        if      (tile == 0) gp = Ahi + (size_t)(row0 + r) * DM_ + k0 + cc * 8; \
        else if (tile == 1) gp = Alo + (size_t)(row0 + r) * DM_ + k0 + cc * 8; \
        else if (tile == 2) gp = Bhi + (size_t)(col0 + r) * DM_ + k0 + cc * 8; \
        else                gp = Blo + (size_t)(col0 + r) * DM_ + k0 + cc * 8; \
        cp16s(so, gp);                                                         \
    }                                                                          \
    CP_COMMIT(); }

#define COMPUTE(s) {                                                                 \
    uint32_t stb = sb + 2048 + (uint32_t)(s) * GST;                                  \
    _Pragma("unroll")                                                                \
    for (int k16 = 0; k16 < 2; k16++) {                                             \
        uint32_t ah[4][4], al[4][4], bh[4][2], bl[4][2];                             \
        _Pragma("unroll")                                                            \
        for (int i = 0; i < 4; i++)                                                  \
            ldsm4(ah[i][0], ah[i][1], ah[i][2], ah[i][3],                            \
                  stb + (uint32_t)((a_row + i*16) * 80 + k16*32 + a_kb));            \
        _Pragma("unroll")                                                            \
        for (int n16 = 0; n16 < 2; n16++)                                            \
            ldsm4(bh[n16*2][0], bh[n16*2][1], bh[n16*2+1][0], bh[n16*2+1][1],        \
                  stb + 20480u + (uint32_t)((b_row + n16*16) * 80 + k16*32 + b_kb)); \
        _Pragma("unroll")                                                            \
        for (int i = 0; i < 4; i++)                                                  \
            _Pragma("unroll")                                                        \
            for (int j = 0; j < 4; j++) mma_bf16(acc[i][j], ah[i], bh[j]);           \
        _Pragma("unroll")                                                            \
        for (int n16 = 0; n16 < 2; n16++)                                            \
            ldsm4(bl[n16*2][0], bl[n16*2][1], bl[n16*2+1][0], bl[n16*2+1][1],        \
                  stb + 30720u + (uint32_t)((b_row + n16*16) * 80 + k16*32 + b_kb)); \
        _Pragma("unroll")                                                            \
        for (int i = 0; i < 4; i++)                                                  \
            _Pragma("unroll")                                                        \
            for (int j = 0; j < 4; j++) mma_bf16(acc[i][j], ah[i], bl[j]);           \
        _Pragma("unroll")                                                            \
        for (int i = 0; i < 4; i++)                                                  \
            ldsm4(al[i][0], al[i][1], al[i][2], al[i][3],                            \
                  stb + 10240u + (uint32_t)((a_row + i*16) * 80 + k16*32 + a_kb));   \
        _Pragma("unroll")                                                            \
        for (int i = 0; i < 4; i++)                                                  \
            _Pragma("unroll")                                                        \
            for (int j = 0; j < 4; j++) mma_bf16(acc[i][j], al[i], bh[j]);           \
    } }

    LOAD_CHUNK(0, 0);
    LOAD_CHUNK(1, 1);

    const int nIter = DM_ / 32;   // 16
#pragma unroll 1
    for (int c = 0; c < nIter; c++) {
        if (c == nIter - 1) { CP_WAIT(0); } else { CP_WAIT(1); }
        __syncthreads();
        COMPUTE(c & 1);
        __syncthreads();
        if (c + 2 < nIter) LOAD_CHUNK(c + 2, c & 1);
    }

    __syncthreads();
#pragma unroll
    for (int i = 0; i < 4; i++) {
#pragma unroll
        for (int j = 0; j < 4; j++) {
            int colg = col0 + warpN * 32 + j * 8 + (lane & 3) * 2;
            int hh = colg >> 6, d0 = colg & 63;
            float b0v = sbias[colg - col0], b1v = sbias[colg - col0 + 1];
#pragma unroll
            for (int half = 0; half < 2; half++) {
                int m = row0 + warpM * 64 + i * 16 + (lane >> 2) + half * 8;
                int b = m >> 12, l = m & 4095;
                float2 v;
                v.x = acc[i][j][half*2 + 0] + b0v;
                v.y = acc[i][j][half*2 + 1] + b1v;
                *(float2*)(jb.c + (((size_t)(b * H_ + hh) * L_) + l) * D_ + d0) = v;
            }
        }
    }
#undef LOAD_CHUNK
#undef COMPUTE
}

// ------- T GEMMs: split-K, atomic accumulate directly into g_Tkv -------
struct TW { const float* b[2]; };
__global__ __launch_bounds__(256)
void sgemm_T_part(const float* __restrict__ A, TW tw) {
    __shared__ float As[16][68];
    __shared__ float Bs[16][64];
    int tid = threadIdx.x, tx = tid & 15, ty = tid >> 4;
    int r0 = blockIdx.y * 64, c0 = blockIdx.x * 64;
    int kc = blockIdx.z & 15, which = blockIdx.z >> 4;
    const float* Bm = tw.b[which];
    float acc[4][4];
#pragma unroll
    for (int i = 0; i < 4; i++)
#pragma unroll
        for (int j = 0; j < 4; j++) acc[i][j] = 0.f;

    for (int kt = kc * 32; kt < kc * 32 + 32; kt += 16) {
        int m = tid >> 2, k4 = tid & 3;
        float4 av = *(const float4*)(A + (size_t)(r0 + m) * DM_ + kt + k4 * 4);
        As[k4*4+0][m] = av.x; As[k4*4+1][m] = av.y;
        As[k4*4+2][m] = av.z; As[k4*4+3][m] = av.w;
        int kk = tid >> 4, n4 = tid & 15;
        *(float4*)&Bs[kk][n4 * 4] = *(const float4*)(Bm + (size_t)(kt + kk) * DM_ + c0 + n4 * 4);
        __syncthreads();
#pragma unroll
        for (int k = 0; k < 16; k++) {
            float a[4], b[4];
            *(float4*)a = *(const float4*)&As[k][ty * 4];
            *(float4*)b = *(const float4*)&Bs[k][tx * 4];
#pragma unroll
            for (int i = 0; i < 4; i++)
#pragma unroll
                for (int j = 0; j < 4; j++) acc[i][j] += a[i] * b[j];
        }
        __syncthreads();
    }
    float* dst = g_Tkv + (size_t)which * DM_ * DM_ + (size_t)(r0 + ty * 4) * DM_ + c0 + tx * 4;
#pragma unroll
    for (int i = 0; i < 4; i++) {
        atomicAdd(dst + (size_t)i * DM_ + 0, acc[i][0]);
        atomicAdd(dst + (size_t)i * DM_ + 1, acc[i][1]);
        atomicAdd(dst + (size_t)i * DM_ + 2, acc[i][2]);
        atomicAdd(dst + (size_t)i * DM_ + 3, acc[i][3]);
    }
}

// ---------------- layer-0 sample_m (dense K, idx table) ----------------
__global__ __launch_bounds__(256)
void sample_m_kernel(const int* __restrict__ idx) {
    int gw = (blockIdx.x * blockDim.x + threadIdx.x) >> 5;
    int lane = threadIdx.x & 31;
    if (gw >= BH_ * L_) return;
    int bh = gw >> 12, l = gw & 4095;
    const float4* qrow = (const float4*)(g_Q + ((size_t)bh * L_ + l) * D_);
    float val = 0.f;
    bool active = lane < NS_;
    if (active) {
        int kk = idx[l * NS_ + lane];
        const float4* krow = (const float4*)(g_K + ((size_t)bh * L_ + kk) * D_);
        float s = 0.f;
#pragma unroll
        for (int d4 = 0; d4 < 16; d4++) {
            float4 q = qrow[d4], k = krow[d4];
            s += q.x*k.x + q.y*k.y + q.z*k.z + q.w*k.w;
        }
        val = s;
    }
    float mx = active ? val : -__int_as_float(0x7f800000);
    float sm = active ? val : 0.f;
#pragma unroll
    for (int off = 16; off > 0; off >>= 1) {
        mx = fmaxf(mx, __shfl_down_sync(0xffffffffu, mx, off));
        sm += __shfl_down_sync(0xffffffffu, sm, off);
    }
    if (lane == 0) g_M[gw] = mx - sm * (1.f / (float)L_);
}

// ---------------- layer-1 sample_m (low-rank K1, idx table) ----------------
__global__ __launch_bounds__(256)
void sample_m1_kernel(const int* __restrict__ idx) {
    int gw = (blockIdx.x * blockDim.x + threadIdx.x) >> 5;
    int lane = threadIdx.x & 31;
    if (gw >= BH_ * L_) return;
    int bh = gw >> 12, l = gw & 4095;
    int b = bh >> 3, h = bh & 7;
    const float4* qrow = (const float4*)(g_Q1 + ((size_t)bh * L_ + l) * D_);
    const float4* brow = (const float4*)(g_basekv + (size_t)b * DM_ + h * D_);
    bool active = lane < NS_;
    int j = -1;
    if (active) {
        int kk = idx[l * NS_ + lane];
        j = g_map[b * L_ + kk];
    }
    float s = 0.f;
#pragma unroll
    for (int d4 = 0; d4 < 16; d4++) {
        float4 q = qrow[d4], bb = brow[d4];
        s += q.x*bb.x + q.y*bb.y + q.z*bb.z + q.w*bb.w;
    }
    if (j >= 0) {
        const float4* crow = (const float4*)(g_ck + ((size_t)(b * SLOTS + j)) * DM_ + h * D_);
#pragma unroll
        for (int d4 = 0; d4 < 16; d4++) {
            float4 q = qrow[d4], c = crow[d4];
            s += q.x*c.x + q.y*c.y + q.z*c.z + q.w*c.w;
        }
    }
    float val = s;
    float mx = active ? val : -__int_as_float(0x7f800000);
    float sm = active ? val : 0.f;
#pragma unroll
    for (int off = 16; off > 0; off >>= 1) {
        mx = fmaxf(mx, __shfl_down_sync(0xffffffffu, mx, off));
        sm += __shfl_down_sync(0xffffffffu, sm, off);
    }
    if (lane == 0) g_M[gw] = mx - sm * (1.f / (float)L_);
}

// ---------------- top-27: cached per-thread max keys (+ optional mark) -----
__device__ __forceinline__ unsigned ordf(float v) {
    unsigned u = __float_as_uint(v);
    return (u & 0x80000000u) ? ~u : (u | 0x80000000u);
}

__global__ __launch_bounds__(256)
void topk_kernel(int domark) {
    int bh = blockIdx.x, t = threadIdx.x;
    int lane = t & 31, wid = t >> 5;
    __shared__ float sm[L_];
    __shared__ unsigned long long wred[8];
    __shared__ unsigned long long sbest;
    for (int i = t; i < L_; i += 256) sm[i] = g_M[(size_t)bh * L_ + i];
    __syncthreads();

    const int base = t * 16;
    unsigned long long myKey = 0ull;
#pragma unroll
    for (int i = 0; i < 16; i++) {
        unsigned long long key = ((unsigned long long)ordf(sm[base + i]) << 32)
                               | (unsigned)(L_ - 1 - (base + i));
        if (key > myKey) myKey = key;
    }

    int bB = bh >> 3;
    for (int it = 0; it < NS_; it++) {
        unsigned long long b = myKey;
#pragma unroll
        for (int off = 16; off > 0; off >>= 1) {
            unsigned long long o = __shfl_down_sync(0xffffffffu, b, off);
            if (o > b) b = o;
        }
        if (lane == 0) wred[wid] = b;
        __syncthreads();
        if (t == 0) {
            unsigned long long b2 = wred[0];
#pragma unroll
            for (int w = 1; w < 8; w++) if (wred[w] > b2) b2 = wred[w];
            sbest = b2;
            int idx = L_ - 1 - (int)(b2 & 0xFFFFFFFFull);
            g_topidx[bh * NS_ + it] = idx;
            if (domark) g_map[bB * L_ + idx] = 1;
        }
        __syncthreads();
        int gi = L_ - 1 - (int)(sbest & 0xFFFFFFFFull);
        if ((gi >> 4) == t) {
            sm[gi] = -__int_as_float(0x7f800000);
            unsigned long long nk = 0ull;
#pragma unroll
            for (int i = 0; i < 16; i++) {
                unsigned long long key = ((unsigned long long)ordf(sm[base + i]) << 32)
                                       | (unsigned)(L_ - 1 - (base + i));
                if (key > nk) nk = key;
            }
            myKey = nk;
        }
    }
}

// ---------------- layer-0 meanV combine (8 chunk partials from att_fused) --
__global__ __launch_bounds__(64)
void meanv2_kernel() {
    int bh = blockIdx.x, d = threadIdx.x;
    float s = 0.f;
#pragma unroll
    for (int c = 0; c < NCH; c++) s += g_vpart[(bh * NCH + c) * D_ + d];
    g_meanV[bh * D_ + d] = s * (1.f / (float)L_);
}

// ---------------- layer-1 meanV (low-rank) ----------------
__global__ __launch_bounds__(64)
void meanv1b_kernel() {
    int bh = blockIdx.x, t = threadIdx.x;
    int b = bh >> 3, h = bh & 7;
    int cnt = g_cnt[b];
    float s = 0.f;
    for (int j = 0; j < cnt; j++)
        s += g_ck[CKOFF + ((size_t)(b * SLOTS + j)) * DM_ + h * D_ + t];
    g_meanV[bh * D_ + t] = g_basekv[(size_t)(B_ + b) * DM_ + h * D_ + t] + s * (1.f / (float)L_);
}

// ---------------- layer-0 fused scores+softmax+pv (+ V chunk sums) ---------
#define ATT_SMEM ((NS_*CH + 64*129 + NS_*64 + 64) * 4)
__global__ __launch_bounds__(256, 2)
void att_fused_kernel() {
    extern __shared__ float smf[];
    float* sS   = smf;
    float* KsT  = smf + NS_ * CH;
    float* sQ   = KsT + 64 * 129;

    int bh = blockIdx.x, ch = blockIdx.y, t = threadIdx.x;
    int lane = t & 31, w = t >> 5;
    int l0 = ch * CH;

    for (int f = t; f < NS_ * 16; f += 256) {
        int u = f >> 4, d4 = f & 15;
        int l = g_topidx[bh * NS_ + u];
        *(float4*)&sQ[u * 64 + d4 * 4] =
            *(const float4*)(g_Q + ((size_t)bh * L_ + l) * D_ + d4 * 4);
    }

    const int ubeg = (t >> 7) ? 14 : 0;
    const int ucnt = (t >> 7) ? 13 : 14;
    const int kk = t & 127;
#pragma unroll 1
    for (int st = 0; st < CH / 128; st++) {
        __syncthreads();
        for (int f = t; f < 128 * 16; f += 256) {
            int kr = f >> 4, d4 = f & 15;
            float4 v = *(const float4*)(g_K + ((size_t)bh * L_ + l0 + st * 128 + kr) * D_ + d4 * 4);
            KsT[(d4*4+0) * 129 + kr] = v.x; KsT[(d4*4+1) * 129 + kr] = v.y;
            KsT[(d4*4+2) * 129 + kr] = v.z; KsT[(d4*4+3) * 129 + kr] = v.w;
        }
        __syncthreads();
        float acc[14];
#pragma unroll
        for (int i = 0; i < 14; i++) acc[i] = 0.f;
#pragma unroll
        for (int d0 = 0; d0 < 64; d0 += 4) {
            float k0 = KsT[d0*129 + kk], k1 = KsT[(d0+1)*129 + kk];
            float k2 = KsT[(d0+2)*129 + kk], k3 = KsT[(d0+3)*129 + kk];
#pragma unroll
            for (int i = 0; i < 14; i++) {
                if (i < ucnt) {
                    float4 q = *(const float4*)&sQ[(ubeg + i) * 64 + d0];
                    acc[i] += q.x*k0 + q.y*k1 + q.z*k2 + q.w*k3;
                }
            }
        }
#pragma unroll
        for (int i = 0; i < 14; i++)
            if (i < ucnt) sS[(ubeg + i) * CH + st * 128 + kk] = acc[i] * 0.125f;
    }
    __syncthreads();

    for (int u = w; u < NS_; u += 8) {
        float mx = -__int_as_float(0x7f800000);
#pragma unroll
        for (int j = 0; j < CH / 32; j++)
            mx = fmaxf(mx, sS[u * CH + lane + j * 32]);
#pragma unroll
        for (int off = 16; off > 0; off >>= 1)
            mx = fmaxf(mx, __shfl_xor_sync(0xffffffffu, mx, off));
        float ss = 0.f;
#pragma unroll
        for (int j = 0; j < CH / 32; j++) {
            float e = __expf(sS[u * CH + lane + j * 32] - mx);
            sS[u * CH + lane + j * 32] = e;
            ss += e;
        }
#pragma unroll
        for (int off = 16; off > 0; off >>= 1)
            ss += __shfl_xor_sync(0xffffffffu, ss, off);
        if (lane == 0) {
            int pi = (bh * NCH + ch) * NS_ + u;
            g_attM[pi] = mx;
            g_attS[pi] = ss;
        }
    }
    __syncthreads();

    int d = t & 63, ug = t >> 6;
    float acc[7];
#pragma unroll
    for (int j = 0; j < 7; j++) acc[j] = 0.f;
    float vsum = 0.f;
    for (int k = 0; k < CH; k += 4) {
        float v0 = g_V[((size_t)bh * L_ + l0 + k + 0) * D_ + d];
        float v1 = g_V[((size_t)bh * L_ + l0 + k + 1) * D_ + d];
        float v2 = g_V[((size_t)bh * L_ + l0 + k + 2) * D_ + d];
        float v3 = g_V[((size_t)bh * L_ + l0 + k + 3) * D_ + d];
        if (ug == 0) vsum += v0 + v1 + v2 + v3;
#pragma unroll
        for (int j = 0; j < 7; j++) {
            int u = ug + j * 4;
            if (u < NS_) {
                float4 p = *(const float4*)&sS[u * CH + k];
                acc[j] += p.x*v0 + p.y*v1 + p.z*v2 + p.w*v3;
            }
        }
    }
    if (ug == 0) g_vpart[(bh * NCH + ch) * D_ + d] = vsum;
#pragma unroll
    for (int j = 0; j < 7; j++) {
        int u = ug + j * 4;
        if (u < NS_)
            g_attO[((size_t)(bh * NCH + ch) * NS_ + u) * D_ + d] = acc[j];
    }
}

__global__ __launch_bounds__(64)
void att_combine_kernel() {
    int bu = blockIdx.x;
    int bh = bu / NS_, u = bu % NS_;
    int d = threadIdx.x;
    float m = -__int_as_float(0x7f800000);
#pragma unroll
    for (int c = 0; c < NCH; c++)
        m = fmaxf(m, g_attM[(bh * NCH + c) * NS_ + u]);
    float s = 0.f, o = 0.f;
#pragma unroll
    for (int c = 0; c < NCH; c++) {
        int pi = (bh * NCH + c) * NS_ + u;
        float wgt = __expf(g_attM[pi] - m);
        s += wgt * g_attS[pi];
        o += wgt * g_attO[(size_t)pi * D_ + d];
    }
    g_outtop[(bh * NS_ + u) * D_ + d] = o / s;
}

// ---------------- layer-1 attention over low-rank K1/V1 ----------------
__global__ __launch_bounds__(256)
void att1_fused_kernel() {
    __shared__ float sQ[64];
    __shared__ float sS[SLOTS];
    __shared__ float red[256];
    __shared__ float sstat[2];
    int bu = blockIdx.x;
    int bh = bu / NS_, u = bu % NS_;
    int b = bh >> 3, h = bh & 7;
    int t = threadIdx.x;
    int cnt = g_cnt[b];
    int lsel = g_topidx[bh * NS_ + u];
    if (t < 64) sQ[t] = g_Q1[((size_t)bh * L_ + lsel) * D_ + t];
    __syncthreads();

    if (t < 32) {
        float p = sQ[t] * g_basekv[(size_t)b * DM_ + h * D_ + t]
                + sQ[t + 32] * g_basekv[(size_t)b * DM_ + h * D_ + t + 32];
#pragma unroll
        for (int off = 16; off > 0; off >>= 1)
            p += __shfl_xor_sync(0xffffffffu, p, off);
        if (t == 0) sstat[0] = 0.125f * p;
    }
    __syncthreads();
    float qb = sstat[0];

    float sj = -__int_as_float(0x7f800000);
    if (t < cnt) {
        const float4* c = (const float4*)(g_ck + ((size_t)(b * SLOTS + t)) * DM_ + h * D_);
        float dot = 0.f;
#pragma unroll
        for (int d4 = 0; d4 < 16; d4++) {
            float4 cv = c[d4];
            dot += sQ[d4*4]*cv.x + sQ[d4*4+1]*cv.y + sQ[d4*4+2]*cv.z + sQ[d4*4+3]*cv.w;
        }
        sj = qb + 0.125f * dot;
        sS[t] = sj;
    }
    red[t] = sj;
    __syncthreads();
    for (int s = 128; s > 0; s >>= 1) {
        if (t < s) red[t] = fmaxf(red[t], red[t + s]);
        __syncthreads();
    }
    float m = fmaxf(red[0], qb);
    __syncthreads();

    float e = 0.f;
    if (t < cnt) { e = __expf(sS[t] - m); sS[t] = e; }
    red[t] = e;
    __syncthreads();
    for (int s = 128; s > 0; s >>= 1) {
        if (t < s) red[t] += red[t + s];
        __syncthreads();
    }
    if (t == 0)
        sstat[1] = 1.f / (red[0] + (float)(L_ - cnt) * __expf(qb - m));
    __syncthreads();
    float inv = sstat[1];

    if (t < 64) {
        float o = 0.f;
        for (int j = 0; j < cnt; j++)
            o += sS[j] * g_ck[CKOFF + ((size_t)(b * SLOTS + j)) * DM_ + h * D_ + t];
        o = o * inv + g_basekv[(size_t)(B_ + b) * DM_ + h * D_ + t];
        g_outtop[(bh * NS_ + u) * D_ + t] = o;
    }
}

// ---------------- slot assignment ----------------
__global__ __launch_bounds__(256)
void slot_assign_kernel() {
    int b = blockIdx.x, t = threadIdx.x;
    __shared__ int cs[256];
    int base = t * 16;
    int c = 0;
#pragma unroll
    for (int i = 0; i < 16; i++)
        if (g_map[b * L_ + base + i] == 1) c++;
    cs[t] = c;
    __syncthreads();
    for (int off = 1; off < 256; off <<= 1) {
        int v = (t >= off) ? cs[t - off] : 0;
        __syncthreads();
        cs[t] += v;
        __syncthreads();
    }
    int slot = cs[t] - c;
#pragma unroll
    for (int i = 0; i < 16; i++) {
        if (g_map[b * L_ + base + i] == 1)
            g_map[b * L_ + base + i] = slot++;
    }
    if (t == 255) g_cnt[b] = cs[255];
}

__global__ __launch_bounds__(128)
void corr_compact_kernel() {
    int blk = blockIdx.x, z = blockIdx.y;
    int bh0 = blk / NS_, u = blk % NS_;
    int b = bh0 >> 3, h0 = bh0 & 7;
    int t = threadIdx.x;
    __shared__ float qv[64];
    if (t < 64) qv[t] = g_outtop[(bh0 * NS_ + u) * 64 + t] - g_meanV[bh0 * 64 + t];
    __syncthreads();
    const float* T = g_Tkv + (size_t)z * DM_ * DM_;
    int l = g_topidx[bh0 * NS_ + u];
    int slot = g_map[b * L_ + l];
    float a0 = 0.f, a1 = 0.f, a2 = 0.f, a3 = 0.f;
#pragma unroll 8
    for (int k = 0; k < 64; k++) {
        float q = qv[k];
        float4 wv = *(const float4*)(T + (size_t)(h0 * 64 + k) * DM_ + t * 4);
        a0 += q * wv.x; a1 += q * wv.y; a2 += q * wv.z; a3 += q * wv.w;
    }
    float* dst = g_ck + (size_t)z * CKOFF + ((size_t)(b * SLOTS + slot)) * DM_ + t * 4;
    atomicAdd(dst + 0, a0); atomicAdd(dst + 1, a1);
    atomicAdd(dst + 2, a2); atomicAdd(dst + 3, a3);
}

// ---------------- generic GEMV: partials then combine ----------------
__global__ __launch_bounds__(512)
void base1g_kernel(const float* __restrict__ invec, const float* __restrict__ w) {
    int b = blockIdx.x, kc = blockIdx.y, n = threadIdx.x;
    __shared__ float mc[64];
    if (n < 64) mc[n] = invec[b * DM_ + kc * 64 + n];
    __syncthreads();
    float s = 0.f;
#pragma unroll 8
    for (int k = 0; k < 64; k++) s += mc[k] * w[(size_t)(kc * 64 + k) * DM_ + n];
    g_basep[(b * 8 + kc) * DM_ + n] = s;
}

__global__ __launch_bounds__(512)
void base2g_kernel(const float* __restrict__ bias, float* __restrict__ outv) {
    int b = blockIdx.x, n = threadIdx.x;
    float s = bias[n];
#pragma unroll
    for (int p = 0; p < 8; p++) s += g_basep[(b * 8 + p) * DM_ + n];
    outv[b * DM_ + n] = s;
}

struct KV2 { const float* w[2]; const float* bias[2]; };
__global__ __launch_bounds__(512)
void basekv1_kernel(const float* __restrict__ invec, KV2 kv) {
    int b = blockIdx.x, kc = blockIdx.y, z = blockIdx.z, n = threadIdx.x;
    __shared__ float mc[64];
    if (n < 64) mc[n] = invec[b * DM_ + kc * 64 + n];
    __syncthreads();
    const float* w = kv.w[z];
    float s = 0.f;
#pragma unroll 8
    for (int k = 0; k < 64; k++) s += mc[k] * w[(size_t)(kc * 64 + k) * DM_ + n];
    g_basep2[((z * B_ + b) * 8 + kc) * DM_ + n] = s;
}

__global__ __launch_bounds__(512)
void basekv2_kernel(KV2 kv) {
    int b = blockIdx.x, z = blockIdx.y, n = threadIdx.x;
    float s = kv.bias[z][n];
#pragma unroll
    for (int p = 0; p < 8; p++) s += g_basep2[((z * B_ + b) * 8 + p) * DM_ + n];
    g_basekv[(z * B_ + b) * DM_ + n] = s;
}

// ---------------- output broadcasts ----------------
__global__ __launch_bounds__(256)
void bcast_out_kernel(const float* __restrict__ xs, float* __restrict__ out,
                      const float* __restrict__ basev, int row_off) {
    int i4 = blockIdx.x * 256 + threadIdx.x;
    int n4 = i4 & 127;
    int l = (i4 >> 7) & 4095;
    int b = i4 / (L_ * 128);
    size_t oi = ((size_t)(b * 8192 + row_off + l)) * 128 + n4;
    float4 a = ((const float4*)xs)[oi];
    float4 s = ((const float4*)basev)[b * 128 + n4];
    a.x += s.x; a.y += s.y; a.z += s.z; a.w += s.w;
    ((float4*)out)[oi] = a;
}

__global__ __launch_bounds__(128)
void corr_kernel(const float* __restrict__ wo, float* __restrict__ dst, int row_off) {
    int blk = blockIdx.x;
    int bh = blk / NS_, u = blk % NS_;
    int b = bh >> 3, h = bh & 7;
    int t = threadIdx.x;
    __shared__ float qv[64];
    if (t < 64) qv[t] = g_outtop[(bh * NS_ + u) * 64 + t] - g_meanV[bh * 64 + t];
    __syncthreads();
    int l = g_topidx[bh * NS_ + u];
    float a0 = 0.f, a1 = 0.f, a2 = 0.f, a3 = 0.f;
#pragma unroll 8
    for (int k = 0; k < 64; k++) {
        float q = qv[k];
        float4 wv = *(const float4*)(wo + (size_t)(h * 64 + k) * DM_ + t * 4);
        a0 += q * wv.x; a1 += q * wv.y; a2 += q * wv.z; a3 += q * wv.w;
    }
    float* d = dst + ((size_t)(b * 8192 + row_off + l)) * DM_ + t * 4;
    atomicAdd(d + 0, a0); atomicAdd(d + 1, a1);
    atomicAdd(d + 2, a2); atomicAdd(d + 3, a3);
}

// ---------------- host orchestration ----------------
extern "C" void kernel_launch(void* const* d_in, const int* in_sizes, int n_in,
                              void* d_out, int out_size) {
    const float* xs  = (const float*)d_in[0];
    const float* xd  = (const float*)d_in[1];
    const float* xp  = (const float*)d_in[2];
    const float* w0q = (const float*)d_in[3];
    const float* w0k = (const float*)d_in[4];
    const float* w0v = (const float*)d_in[5];
    const float* w0o = (const float*)d_in[6];
    const float* b0q = (const float*)d_in[7];
    const float* b0k = (const float*)d_in[8];
    const float* b0v = (const float*)d_in[9];
    const float* b0o = (const float*)d_in[10];
    const float* w1q = (const float*)d_in[11];
    const float* w1k = (const float*)d_in[12];
    const float* w1v = (const float*)d_in[13];
    const float* w1o = (const float*)d_in[14];
    const float* b1q = (const float*)d_in[15];
    const float* b1k = (const float*)d_in[16];
    const float* b1v = (const float*)d_in[17];
    const float* b1o = (const float*)d_in[18];
    float* out = (float*)d_out;

    float *pQ, *pQ1, *pK, *pV, *pmv, *pb0, *pb1, *pck, *pTkv;
    int *pidxA, *pidxB, *pmap;
    __nv_bfloat16 *pAxdH, *pAxdL, *pAxpH, *pAxpL, *pWtH, *pWtL;
    cudaGetSymbolAddress((void**)&pQ, g_Q);
    cudaGetSymbolAddress((void**)&pQ1, g_Q1);
    cudaGetSymbolAddress((void**)&pK, g_K);
    cudaGetSymbolAddress((void**)&pV, g_V);
    cudaGetSymbolAddress((void**)&pmv, g_meanV);
    cudaGetSymbolAddress((void**)&pb0, g_base0);
    cudaGetSymbolAddress((void**)&pb1, g_base1);
    cudaGetSymbolAddress((void**)&pck, g_ck);
    cudaGetSymbolAddress((void**)&pTkv, g_Tkv);
    cudaGetSymbolAddress((void**)&pmap, g_map);
    cudaGetSymbolAddress((void**)&pidxA, g_idxA);
    cudaGetSymbolAddress((void**)&pidxB, g_idxB);
    cudaGetSymbolAddress((void**)&pAxdH, g_Axd_hi);
    cudaGetSymbolAddress((void**)&pAxdL, g_Axd_lo);
    cudaGetSymbolAddress((void**)&pAxpH, g_Axp_hi);
    cudaGetSymbolAddress((void**)&pAxpL, g_Axp_lo);
    cudaGetSymbolAddress((void**)&pWtH, g_Wt_hi);
    cudaGetSymbolAddress((void**)&pWtL, g_Wt_lo);

    cudaFuncSetAttribute(gemm_mma4, cudaFuncAttributeMaxDynamicSharedMemorySize, GSMEM);
    cudaFuncSetAttribute(att_fused_kernel, cudaFuncAttributeMaxDynamicSharedMemorySize, ATT_SMEM);

    // scratch init
    cudaMemsetAsync(pmap, 0xFF, (size_t)B_ * L_ * sizeof(int));
    cudaMemsetAsync(pck, 0, (size_t)2 * B_ * SLOTS * DM_ * sizeof(float));
    cudaMemsetAsync(pTkv, 0, (size_t)2 * DM_ * DM_ * sizeof(float));

    // idx tables
    {
        unsigned a42, b42, a43, b43;
        tf2x32(0u, 42u, 0u, 1u, &a42, &b42);
        tf2x32(0u, 43u, 0u, 1u, &a43, &b43);
        IdxKeys ik;
        ik.k0[0] = a42; ik.k1[0] = b42; ik.out[0] = pidxA;
        ik.k0[1] = a43; ik.k1[1] = b43; ik.out[1] = pidxB;
        idx2_kernel<<<dim3((L_ * NS_ + 255) / 256, 2), 256>>>(ik);
    }

    W4 ws;
    ws.w[0] = w0q; ws.w[1] = w0k; ws.w[2] = w0v; ws.w[3] = w1q;
    wt_cvt_all_kernel<<<dim3(16, 16, 4), dim3(32, 32)>>>(ws, pWtH, pWtL);

    // T = Wo0 @ W1{k,v}: split-K with direct atomic accumulation
    TW tw; tw.b[0] = w1k; tw.b[1] = w1v;
    sgemm_T_part<<<dim3(8, 8, 32), 256>>>(w0o, tw);

    const int N4 = BL_ * DM_ / 4;     // 2097152
    const int N4Q = N4 / 4;           // 524288
    {
        Cvt2 c;
        c.src[0] = (const float4*)xd; c.src[1] = (const float4*)xp;
        c.hi[0] = (__nv_bfloat162*)pAxdH; c.hi[1] = (__nv_bfloat162*)pAxpH;
        c.lo[0] = (__nv_bfloat162*)pAxdL; c.lo[1] = (__nv_bfloat162*)pAxpL;
        cvt_pair2_kernel<<<dim3(N4Q / 256, 2), 256>>>(c, N4Q);
    }

    // ---- ALL 4 dense GEMMs in one launch (Q0, K0, V0, Q1) ----
    {
        G4 g4;
        size_t WS = (size_t)DM_ * DM_;
        g4.j[0].ahi = pAxpH; g4.j[0].alo = pAxpL; g4.j[0].bhi = pWtH + 0*WS; g4.j[0].blo = pWtL + 0*WS; g4.j[0].bias = b0q; g4.j[0].c = pQ;
        g4.j[1].ahi = pAxdH; g4.j[1].alo = pAxdL; g4.j[1].bhi = pWtH + 1*WS; g4.j[1].blo = pWtL + 1*WS; g4.j[1].bias = b0k; g4.j[1].c = pK;
        g4.j[2].ahi = pAxdH; g4.j[2].alo = pAxdL; g4.j[2].bhi = pWtH + 2*WS; g4.j[2].blo = pWtL + 2*WS; g4.j[2].bias = b0v; g4.j[2].c = pV;
        g4.j[3].ahi = pAxdH; g4.j[3].alo = pAxdL; g4.j[3].bhi = pWtH + 3*WS; g4.j[3].blo = pWtL + 3*WS; g4.j[3].bias = b1q; g4.j[3].c = pQ1;
        gemm_mma4<<<dim3(DM_ / 128, BL_ / 128, 4), 256, GSMEM>>>(g4);
    }

    // ---- layer 0 attention ----
    sample_m_kernel<<<(BH_ * L_) / 8, 256>>>(pidxA);
    topk_kernel<<<BH_, 256>>>(1);         // also marks g_map
    att_fused_kernel<<<dim3(BH_, NCH), 256, ATT_SMEM>>>();   // also emits V chunk sums
    meanv2_kernel<<<BH_, 64>>>();
    att_combine_kernel<<<BH_ * NS_, 64>>>();

    // base0 = meanctx0 @ Wo0 + bo0
    base1g_kernel<<<dim3(B_, 8), 512>>>(pmv, w0o);
    base2g_kernel<<<B_, 512>>>(b0o, pb0);

    // output upper half (xp2)
    bcast_out_kernel<<<(B_ * L_ * 128) / 256, 256>>>(xs, out, pb0, 4096);
    corr_kernel<<<BH_ * NS_, 128>>>(w0o, out, 4096);

    // ---- compact low-rank K1/V1 ----
    slot_assign_kernel<<<B_, 256>>>();
    corr_compact_kernel<<<dim3(BH_ * NS_, 2), 128>>>();
    {
        KV2 kv;
        kv.w[0] = w1k; kv.w[1] = w1v;
        kv.bias[0] = b1k; kv.bias[1] = b1v;
        basekv1_kernel<<<dim3(B_, 8, 2), 512>>>(pb0, kv);
        basekv2_kernel<<<dim3(B_, 2), 512>>>(kv);
    }

    // ---- layer 1 attention (low-rank K1/V1, Q from g_Q1) ----
    sample_m1_kernel<<<(BH_ * L_) / 8, 256>>>(pidxB);
    topk_kernel<<<BH_, 256>>>(0);
    meanv1b_kernel<<<BH_, 64>>>();
    att1_fused_kernel<<<BH_ * NS_, 256>>>();

    // base1 + output lower half (xd2)
    base1g_kernel<<<dim3(B_, 8), 512>>>(pmv, w1o);
    base2g_kernel<<<B_, 512>>>(b1o, pb1);
    bcast_out_kernel<<<(B_ * L_ * 128) / 256, 256>>>(xs, out, pb1, 0);
    corr_kernel<<<BH_ * NS_, 128>>>(w1o, out, 0);
}

// round 16
// speedup vs baseline: 1.0196x; 1.0196x over previous
#include <cuda_runtime.h>
#include <cuda_bf16.h>
#include <math.h>
#include <stdint.h>

#define B_   4
#define H_   8
#define L_   4096
#define D_   64
#define DM_  512
#define NS_  27
#define BH_  (B_*H_)
#define BL_  (B_*L_)
#define NCH  8
#define CH   (L_/NCH)   // 512
#define SLOTS 216
#define CKOFF ((size_t)B_*SLOTS*DM_)

// ---------------- scratch (device globals; no runtime alloc) ----------------
__device__ float g_Q[BH_*L_*D_];
__device__ float g_Q1[BH_*L_*D_];
__device__ float g_K[BH_*L_*D_];
__device__ float g_V[BH_*L_*D_];
__device__ float g_M[BH_*L_];
__device__ float g_outtop[BH_*NS_*D_];
__device__ float g_meanV[BH_*D_];
__device__ float g_vpart[BH_*16*D_];
__device__ float g_attM[BH_*NCH*NS_];
__device__ float g_attS[BH_*NCH*NS_];
__device__ float g_attO[BH_*NCH*NS_*D_];
__device__ float g_base0[B_*DM_];
__device__ float g_base1[B_*DM_];
__device__ float g_basekv[2*B_*DM_];
__device__ float g_basep[B_*8*DM_];
__device__ float g_basep2[2*B_*8*DM_];
__device__ float g_Tkv[2*DM_*DM_];
__device__ float g_ck[2*B_*SLOTS*DM_];     // [0]=K corrections, [CKOFF]=V corrections
__device__ int   g_map[B_*L_];
__device__ int   g_cnt[B_];
__device__ int   g_idxA[L_*NS_];
__device__ int   g_idxB[L_*NS_];
__device__ int   g_topidx[BH_*NS_];

// bf16-split operand buffers
__device__ __nv_bfloat16 g_Axd_hi[(size_t)BL_*DM_];
__device__ __nv_bfloat16 g_Axd_lo[(size_t)BL_*DM_];
__device__ __nv_bfloat16 g_Axp_hi[(size_t)BL_*DM_];
__device__ __nv_bfloat16 g_Axp_lo[(size_t)BL_*DM_];
__device__ __nv_bfloat16 g_Wt_hi[4*DM_*DM_];   // w0q, w0k, w0v, w1q
__device__ __nv_bfloat16 g_Wt_lo[4*DM_*DM_];

// ---------------- Threefry-2x32 (JAX-exact) ----------------
__host__ __device__ __forceinline__ void tf2x32(unsigned k0, unsigned k1,
                                                unsigned x0, unsigned x1,
                                                unsigned* o0, unsigned* o1) {
    unsigned ks0 = k0, ks1 = k1, ks2 = 0x1BD11BDAu ^ k0 ^ k1;
    x0 += ks0; x1 += ks1;
#define TF_RND(r) { x0 += x1; x1 = (x1 << (r)) | (x1 >> (32 - (r))); x1 ^= x0; }
    TF_RND(13) TF_RND(15) TF_RND(26) TF_RND(6)   x0 += ks1; x1 += ks2 + 1u;
    TF_RND(17) TF_RND(29) TF_RND(16) TF_RND(24)  x0 += ks2; x1 += ks0 + 2u;
    TF_RND(13) TF_RND(15) TF_RND(26) TF_RND(6)   x0 += ks0; x1 += ks1 + 3u;
    TF_RND(17) TF_RND(29) TF_RND(16) TF_RND(24)  x0 += ks1; x1 += ks2 + 4u;
    TF_RND(13) TF_RND(15) TF_RND(26) TF_RND(6)   x0 += ks2; x1 += ks0 + 5u;
#undef TF_RND
    *o0 = x0; *o1 = x1;
}

struct IdxKeys { unsigned k0[2], k1[2]; int* out[2]; };
__global__ void idx2_kernel(IdxKeys ik) {
    int i = blockIdx.x * blockDim.x + threadIdx.x;
    if (i >= L_*NS_) return;
    int z = blockIdx.y;
    unsigned o0, o1;
    tf2x32(ik.k0[z], ik.k1[z], 0u, (unsigned)i, &o0, &o1);
    ik.out[z][i] = (int)((o0 ^ o1) & 4095u);
}

// ---------------- bf16-split conversion (MLP=4, both inputs one launch) ----
struct Cvt2 { const float4* src[2]; __nv_bfloat162* hi[2]; __nv_bfloat162* lo[2]; };
__global__ __launch_bounds__(256)
void cvt_pair2_kernel(Cvt2 c, int n4q) {   // n4q = N4/4
    int z = blockIdx.y;
    int i = blockIdx.x * 256 + threadIdx.x;
    if (i >= n4q) return;
    const float4* __restrict__ src = c.src[z];
    __nv_bfloat162* __restrict__ hi = c.hi[z];
    __nv_bfloat162* __restrict__ lo = c.lo[z];
    float4 v[4];
#pragma unroll
    for (int j = 0; j < 4; j++) v[j] = src[i + j * n4q];
#pragma unroll
    for (int j = 0; j < 4; j++) {
        int ii = i + j * n4q;
        float4 w = v[j];
        __nv_bfloat16 h0 = __float2bfloat16(w.x), h1 = __float2bfloat16(w.y);
        __nv_bfloat16 h2 = __float2bfloat16(w.z), h3 = __float2bfloat16(w.w);
        __nv_bfloat16 l0 = __float2bfloat16(w.x - __bfloat162float(h0));
        __nv_bfloat16 l1 = __float2bfloat16(w.y - __bfloat162float(h1));
        __nv_bfloat16 l2 = __float2bfloat16(w.z - __bfloat162float(h2));
        __nv_bfloat16 l3 = __float2bfloat16(w.w - __bfloat162float(h3));
        hi[ii*2]   = __nv_bfloat162(h0, h1);
        hi[ii*2+1] = __nv_bfloat162(h2, h3);
        lo[ii*2]   = __nv_bfloat162(l0, l1);
        lo[ii*2+1] = __nv_bfloat162(l2, l3);
    }
}

struct W4 { const float* w[4]; };
__global__ __launch_bounds__(1024)
void wt_cvt_all_kernel(W4 ws, __nv_bfloat16* __restrict__ hi, __nv_bfloat16* __restrict__ lo) {
    __shared__ float t[32][33];
    int tx = threadIdx.x, ty = threadIdx.y;
    int n0 = blockIdx.x * 32, k0 = blockIdx.y * 32;
    int z = blockIdx.z;
    const float* W = ws.w[z];
    size_t off = (size_t)z * DM_ * DM_;
    t[ty][tx] = W[(size_t)(k0 + ty) * DM_ + n0 + tx];
    __syncthreads();
    float v = t[tx][ty];
    int n = n0 + ty, k = k0 + tx;
    __nv_bfloat16 h = __float2bfloat16(v);
    hi[off + (size_t)n * DM_ + k] = h;
    lo[off + (size_t)n * DM_ + k] = __float2bfloat16(v - __bfloat162float(h));
}

// ---------------- PTX helpers ----------------
__device__ __forceinline__ void cp16s(uint32_t saddr, const void* g) {
    asm volatile("cp.async.cg.shared.global [%0], [%1], 16;\n" :: "r"(saddr), "l"(g));
}
#define CP_COMMIT() asm volatile("cp.async.commit_group;\n" ::: "memory")
#define CP_WAIT(n)  asm volatile("cp.async.wait_group %0;\n" :: "n"(n) : "memory")

__device__ __forceinline__ void ldsm4(uint32_t& r0, uint32_t& r1, uint32_t& r2, uint32_t& r3,
                                      uint32_t saddr) {
    asm volatile("ldmatrix.sync.aligned.m8n8.x4.shared.b16 {%0,%1,%2,%3}, [%4];"
                 : "=r"(r0), "=r"(r1), "=r"(r2), "=r"(r3) : "r"(saddr));
}

__device__ __forceinline__ void mma_bf16(float* c, const uint32_t* a, const uint32_t* b) {
    asm volatile("mma.sync.aligned.m16n8k16.row.col.f32.bf16.bf16.f32 "
                 "{%0,%1,%2,%3}, {%4,%5,%6,%7}, {%8,%9}, {%0,%1,%2,%3};"
                 : "+f"(c[0]), "+f"(c[1]), "+f"(c[2]), "+f"(c[3])
                 : "r"(a[0]), "r"(a[1]), "r"(a[2]), "r"(a[3]), "r"(b[0]), "r"(b[1]));
}

// ---------------- mma.sync bf16-split GEMM (BK=32, 2-stage, 2 CTAs/SM) -----
#define GST    40960
#define GSMEM  (2048 + 2*GST)

struct GJob { const __nv_bfloat16 *ahi, *alo, *bhi, *blo; const float* bias; float* c; };
struct G4 { GJob j[4]; };

__global__ __launch_bounds__(256, 2)
void gemm_mma4(G4 g4) {
    extern __shared__ char smem[];
    const uint32_t sb = (uint32_t)__cvta_generic_to_shared(smem);
    const int tid = threadIdx.x;
    const int lane = tid & 31, wid = tid >> 5;
    const int warpM = wid >> 2, warpN = wid & 3;
    const int row0 = blockIdx.y * 128, col0 = blockIdx.x * 128;
    GJob jb = g4.j[blockIdx.z];
    const __nv_bfloat16* __restrict__ Ahi = jb.ahi;
    const __nv_bfloat16* __restrict__ Alo = jb.alo;
    const __nv_bfloat16* __restrict__ Bhi = jb.bhi;
    const __nv_bfloat16* __restrict__ Blo = jb.blo;

    float* sbias = (float*)smem;
    if (tid < 128) sbias[tid] = jb.bias[col0 + tid];

    float acc[4][4][4];
#pragma unroll
    for (int i = 0; i < 4; i++)
#pragma unroll
        for (int j = 0; j < 4; j++)
#pragma unroll
            for (int r = 0; r < 4; r++) acc[i][j][r] = 0.f;

    const int a_row = warpM * 64 + (lane & 15);
    const int a_kb  = ((lane >> 4) * 8) * 2;
    const int b_row = warpN * 32 + (lane & 7) + ((lane >> 4) & 1) * 8;
    const int b_kb  = (((lane >> 3) & 1) * 8) * 2;

#define LOAD_CHUNK(c, s) {                                                     \
    uint32_t stb = sb + 2048 + (uint32_t)(s) * GST;                            \
    int k0 = (c) * 32;                                                         \
    _Pragma("unroll")                                                          \
    for (int j = 0; j < 8; j++) {                                              \
        int idx = tid + j * 256;                                               \
        int tile = idx >> 9, w = idx & 511;                                    \
        int r = w >> 2, cc = w & 3;                                            \
        uint32_t so = stb + (uint32_t)tile * 10240u + (uint32_t)(r * 80 + cc * 16); \
        const __nv_bfloat16* gp;                                               \
        if      (tile == 0) gp = Ahi + (size_t)(row0 + r) * DM_ + k0 + cc * 8; \
        else if (tile == 1) gp = Alo + (size_t)(row0 + r) * DM_ + k0 + cc * 8; \
        else if (tile == 2) gp = Bhi + (size_t)(col0 + r) * DM_ + k0 + cc * 8; \
        else                gp = Blo + (size_t)(col0 + r) * DM_ + k0 + cc * 8; \
        cp16s(so, gp);                                                         \
    }                                                                          \
    CP_COMMIT(); }

#define COMPUTE(s) {                                                                 \
    uint32_t stb = sb + 2048 + (uint32_t)(s) * GST;                                  \
    _Pragma("unroll")                                                                \
    for (int k16 = 0; k16 < 2; k16++) {                                             \
        uint32_t ah[4][4], al[4][4], bh[4][2], bl[4][2];                             \
        _Pragma("unroll")                                                            \
        for (int i = 0; i < 4; i++)                                                  \
            ldsm4(ah[i][0], ah[i][1], ah[i][2], ah[i][3],                            \
                  stb + (uint32_t)((a_row + i*16) * 80 + k16*32 + a_kb));            \
        _Pragma("unroll")                                                            \
        for (int n16 = 0; n16 < 2; n16++)                                            \
            ldsm4(bh[n16*2][0], bh[n16*2][1], bh[n16*2+1][0], bh[n16*2+1][1],        \
                  stb + 20480u + (uint32_t)((b_row + n16*16) * 80 + k16*32 + b_kb)); \
        _Pragma("unroll")                                                            \
        for (int i = 0; i < 4; i++)                                                  \
            _Pragma("unroll")                                                        \
            for (int j = 0; j < 4; j++) mma_bf16(acc[i][j], ah[i], bh[j]);           \
        _Pragma("unroll")                                                            \
        for (int n16 = 0; n16 < 2; n16++)                                            \
            ldsm4(bl[n16*2][0], bl[n16*2][1], bl[n16*2+1][0], bl[n16*2+1][1],        \
                  stb + 30720u + (uint32_t)((b_row + n16*16) * 80 + k16*32 + b_kb)); \
        _Pragma("unroll")                                                            \
        for (int i = 0; i < 4; i++)                                                  \
            _Pragma("unroll")                                                        \
            for (int j = 0; j < 4; j++) mma_bf16(acc[i][j], ah[i], bl[j]);           \
        _Pragma("unroll")                                                            \
        for (int i = 0; i < 4; i++)                                                  \
            ldsm4(al[i][0], al[i][1], al[i][2], al[i][3],                            \
                  stb + 10240u + (uint32_t)((a_row + i*16) * 80 + k16*32 + a_kb));   \
        _Pragma("unroll")                                                            \
        for (int i = 0; i < 4; i++)                                                  \
            _Pragma("unroll")                                                        \
            for (int j = 0; j < 4; j++) mma_bf16(acc[i][j], al[i], bh[j]);           \
    } }

    LOAD_CHUNK(0, 0);
    LOAD_CHUNK(1, 1);

    const int nIter = DM_ / 32;   // 16
#pragma unroll 1
    for (int c = 0; c < nIter; c++) {
        if (c == nIter - 1) { CP_WAIT(0); } else { CP_WAIT(1); }
        __syncthreads();
        COMPUTE(c & 1);
        __syncthreads();
        if (c + 2 < nIter) LOAD_CHUNK(c + 2, c & 1);
    }

    __syncthreads();
#pragma unroll
    for (int i = 0; i < 4; i++) {
#pragma unroll
        for (int j = 0; j < 4; j++) {
            int colg = col0 + warpN * 32 + j * 8 + (lane & 3) * 2;
            int hh = colg >> 6, d0 = colg & 63;
            float b0v = sbias[colg - col0], b1v = sbias[colg - col0 + 1];
#pragma unroll
            for (int half = 0; half < 2; half++) {
                int m = row0 + warpM * 64 + i * 16 + (lane >> 2) + half * 8;
                int b = m >> 12, l = m & 4095;
                float2 v;
                v.x = acc[i][j][half*2 + 0] + b0v;
                v.y = acc[i][j][half*2 + 1] + b1v;
                *(float2*)(jb.c + (((size_t)(b * H_ + hh) * L_) + l) * D_ + d0) = v;
            }
        }
    }
#undef LOAD_CHUNK
#undef COMPUTE
}

// ------- T GEMMs: split-K, atomic accumulate directly into g_Tkv -------
struct TW { const float* b[2]; };
__global__ __launch_bounds__(256)
void sgemm_T_part(const float* __restrict__ A, TW tw) {
    __shared__ float As[16][68];
    __shared__ float Bs[16][64];
    int tid = threadIdx.x, tx = tid & 15, ty = tid >> 4;
    int r0 = blockIdx.y * 64, c0 = blockIdx.x * 64;
    int kc = blockIdx.z & 15, which = blockIdx.z >> 4;
    const float* Bm = tw.b[which];
    float acc[4][4];
#pragma unroll
    for (int i = 0; i < 4; i++)
#pragma unroll
        for (int j = 0; j < 4; j++) acc[i][j] = 0.f;

    for (int kt = kc * 32; kt < kc * 32 + 32; kt += 16) {
        int m = tid >> 2, k4 = tid & 3;
        float4 av = *(const float4*)(A + (size_t)(r0 + m) * DM_ + kt + k4 * 4);
        As[k4*4+0][m] = av.x; As[k4*4+1][m] = av.y;
        As[k4*4+2][m] = av.z; As[k4*4+3][m] = av.w;
        int kk = tid >> 4, n4 = tid & 15;
        *(float4*)&Bs[kk][n4 * 4] = *(const float4*)(Bm + (size_t)(kt + kk) * DM_ + c0 + n4 * 4);
        __syncthreads();
#pragma unroll
        for (int k = 0; k < 16; k++) {
            float a[4], b[4];
            *(float4*)a = *(const float4*)&As[k][ty * 4];
            *(float4*)b = *(const float4*)&Bs[k][tx * 4];
#pragma unroll
            for (int i = 0; i < 4; i++)
#pragma unroll
                for (int j = 0; j < 4; j++) acc[i][j] += a[i] * b[j];
        }
        __syncthreads();
    }
    float* dst = g_Tkv + (size_t)which * DM_ * DM_ + (size_t)(r0 + ty * 4) * DM_ + c0 + tx * 4;
#pragma unroll
    for (int i = 0; i < 4; i++) {
        atomicAdd(dst + (size_t)i * DM_ + 0, acc[i][0]);
        atomicAdd(dst + (size_t)i * DM_ + 1, acc[i][1]);
        atomicAdd(dst + (size_t)i * DM_ + 2, acc[i][2]);
        atomicAdd(dst + (size_t)i * DM_ + 3, acc[i][3]);
    }
}

// ---------------- layer-0 sample_m (dense K, idx table) ----------------
__global__ __launch_bounds__(256)
void sample_m_kernel(const int* __restrict__ idx) {
    int gw = (blockIdx.x * blockDim.x + threadIdx.x) >> 5;
    int lane = threadIdx.x & 31;
    if (gw >= BH_ * L_) return;
    int bh = gw >> 12, l = gw & 4095;
    const float4* qrow = (const float4*)(g_Q + ((size_t)bh * L_ + l) * D_);
    float val = 0.f;
    bool active = lane < NS_;
    if (active) {
        int kk = idx[l * NS_ + lane];
        const float4* krow = (const float4*)(g_K + ((size_t)bh * L_ + kk) * D_);
        float s = 0.f;
#pragma unroll
        for (int d4 = 0; d4 < 16; d4++) {
            float4 q = qrow[d4], k = krow[d4];
            s += q.x*k.x + q.y*k.y + q.z*k.z + q.w*k.w;
        }
        val = s;
    }
    float mx = active ? val : -__int_as_float(0x7f800000);
    float sm = active ? val : 0.f;
#pragma unroll
    for (int off = 16; off > 0; off >>= 1) {
        mx = fmaxf(mx, __shfl_down_sync(0xffffffffu, mx, off));
        sm += __shfl_down_sync(0xffffffffu, sm, off);
    }
    if (lane == 0) g_M[gw] = mx - sm * (1.f / (float)L_);
}

// ---------------- layer-1 sample_m (low-rank K1, idx table) ----------------
__global__ __launch_bounds__(256)
void sample_m1_kernel(const int* __restrict__ idx) {
    int gw = (blockIdx.x * blockDim.x + threadIdx.x) >> 5;
    int lane = threadIdx.x & 31;
    if (gw >= BH_ * L_) return;
    int bh = gw >> 12, l = gw & 4095;
    int b = bh >> 3, h = bh & 7;
    const float4* qrow = (const float4*)(g_Q1 + ((size_t)bh * L_ + l) * D_);
    const float4* brow = (const float4*)(g_basekv + (size_t)b * DM_ + h * D_);
    bool active = lane < NS_;
    int j = -1;
    if (active) {
        int kk = idx[l * NS_ + lane];
        j = g_map[b * L_ + kk];
    }
    float s = 0.f;
#pragma unroll
    for (int d4 = 0; d4 < 16; d4++) {
        float4 q = qrow[d4], bb = brow[d4];
        s += q.x*bb.x + q.y*bb.y + q.z*bb.z + q.w*bb.w;
    }
    if (j >= 0) {
        const float4* crow = (const float4*)(g_ck + ((size_t)(b * SLOTS + j)) * DM_ + h * D_);
#pragma unroll
        for (int d4 = 0; d4 < 16; d4++) {
            float4 q = qrow[d4], c = crow[d4];
            s += q.x*c.x + q.y*c.y + q.z*c.z + q.w*c.w;
        }
    }
    float val = s;
    float mx = active ? val : -__int_as_float(0x7f800000);
    float sm = active ? val : 0.f;
#pragma unroll
    for (int off = 16; off > 0; off >>= 1) {
        mx = fmaxf(mx, __shfl_down_sync(0xffffffffu, mx, off));
        sm += __shfl_down_sync(0xffffffffu, sm, off);
    }
    if (lane == 0) g_M[gw] = mx - sm * (1.f / (float)L_);
}

// ---------------- top-27: cached per-thread max keys (+ optional mark) -----
__device__ __forceinline__ unsigned ordf(float v) {
    unsigned u = __float_as_uint(v);
    return (u & 0x80000000u) ? ~u : (u | 0x80000000u);
}

__global__ __launch_bounds__(256)
void topk_kernel(int domark) {
    int bh = blockIdx.x, t = threadIdx.x;
    int lane = t & 31, wid = t >> 5;
    __shared__ float sm[L_];
    __shared__ unsigned long long wred[8];
    __shared__ unsigned long long sbest;
    for (int i = t; i < L_; i += 256) sm[i] = g_M[(size_t)bh * L_ + i];
    __syncthreads();

    const int base = t * 16;
    unsigned long long myKey = 0ull;
#pragma unroll
    for (int i = 0; i < 16; i++) {
        unsigned long long key = ((unsigned long long)ordf(sm[base + i]) << 32)
                               | (unsigned)(L_ - 1 - (base + i));
        if (key > myKey) myKey = key;
    }

    int bB = bh >> 3;
    for (int it = 0; it < NS_; it++) {
        unsigned long long b = myKey;
#pragma unroll
        for (int off = 16; off > 0; off >>= 1) {
            unsigned long long o = __shfl_down_sync(0xffffffffu, b, off);
            if (o > b) b = o;
        }
        if (lane == 0) wred[wid] = b;
        __syncthreads();
        if (t == 0) {
            unsigned long long b2 = wred[0];
#pragma unroll
            for (int w = 1; w < 8; w++) if (wred[w] > b2) b2 = wred[w];
            sbest = b2;
            int idx = L_ - 1 - (int)(b2 & 0xFFFFFFFFull);
            g_topidx[bh * NS_ + it] = idx;
            if (domark) g_map[bB * L_ + idx] = 1;
        }
        __syncthreads();
        int gi = L_ - 1 - (int)(sbest & 0xFFFFFFFFull);
        if ((gi >> 4) == t) {
            sm[gi] = -__int_as_float(0x7f800000);
            unsigned long long nk = 0ull;
#pragma unroll
            for (int i = 0; i < 16; i++) {
                unsigned long long key = ((unsigned long long)ordf(sm[base + i]) << 32)
                                       | (unsigned)(L_ - 1 - (base + i));
                if (key > nk) nk = key;
            }
            myKey = nk;
        }
    }
}

// ---------------- layer-0 meanV: two-stage ----------------
__global__ __launch_bounds__(256)
void meanv1_kernel() {
    int bh = blockIdx.x, c = blockIdx.y, t = threadIdx.x;
    int d = t & 63, r = t >> 6;
    float s = 0.f;
    int base = c * 256;
    for (int l = base + r; l < base + 256; l += 4)
        s += g_V[((size_t)bh * L_ + l) * D_ + d];
    __shared__ float red[256];
    red[t] = s; __syncthreads();
    if (t < 64)
        g_vpart[(bh * 16 + c) * D_ + d] = red[d] + red[64+d] + red[128+d] + red[192+d];
}

// ---------------- merged meanv2 + att_combine (both 64-thread blocks) ------
__global__ __launch_bounds__(64)
void combine2_kernel() {
    int bid = blockIdx.x;
    int d = threadIdx.x;
    if (bid < BH_ * NS_) {
        int bh = bid / NS_, u = bid % NS_;
        float m = -__int_as_float(0x7f800000);
#pragma unroll
        for (int c = 0; c < NCH; c++)
            m = fmaxf(m, g_attM[(bh * NCH + c) * NS_ + u]);
        float s = 0.f, o = 0.f;
#pragma unroll
        for (int c = 0; c < NCH; c++) {
            int pi = (bh * NCH + c) * NS_ + u;
            float wgt = __expf(g_attM[pi] - m);
            s += wgt * g_attS[pi];
            o += wgt * g_attO[(size_t)pi * D_ + d];
        }
        g_outtop[(bh * NS_ + u) * D_ + d] = o / s;
    } else {
        int bh = bid - BH_ * NS_;
        float s = 0.f;
#pragma unroll
        for (int c = 0; c < 16; c++) s += g_vpart[(bh * 16 + c) * D_ + d];
        g_meanV[bh * D_ + d] = s * (1.f / (float)L_);
    }
}

// ---------------- layer-1 meanV (low-rank) ----------------
__global__ __launch_bounds__(64)
void meanv1b_kernel() {
    int bh = blockIdx.x, t = threadIdx.x;
    int b = bh >> 3, h = bh & 7;
    int cnt = g_cnt[b];
    float s = 0.f;
    for (int j = 0; j < cnt; j++)
        s += g_ck[CKOFF + ((size_t)(b * SLOTS + j)) * DM_ + h * D_ + t];
    g_meanV[bh * D_ + t] = g_basekv[(size_t)(B_ + b) * DM_ + h * D_ + t] + s * (1.f / (float)L_);
}

// ---------------- layer-0 fused scores+softmax+pv ----------------
#define ATT_SMEM ((NS_*CH + 64*129 + NS_*64 + 64) * 4)
__global__ __launch_bounds__(256, 2)
void att_fused_kernel() {
    extern __shared__ float smf[];
    float* sS   = smf;
    float* KsT  = smf + NS_ * CH;
    float* sQ   = KsT + 64 * 129;

    int bh = blockIdx.x, ch = blockIdx.y, t = threadIdx.x;
    int lane = t & 31, w = t >> 5;
    int l0 = ch * CH;

    for (int f = t; f < NS_ * 16; f += 256) {
        int u = f >> 4, d4 = f & 15;
        int l = g_topidx[bh * NS_ + u];
        *(float4*)&sQ[u * 64 + d4 * 4] =
            *(const float4*)(g_Q + ((size_t)bh * L_ + l) * D_ + d4 * 4);
    }

    const int ubeg = (t >> 7) ? 14 : 0;
    const int ucnt = (t >> 7) ? 13 : 14;
    const int kk = t & 127;
#pragma unroll 1
    for (int st = 0; st < CH / 128; st++) {
        __syncthreads();
        for (int f = t; f < 128 * 16; f += 256) {
            int kr = f >> 4, d4 = f & 15;
            float4 v = *(const float4*)(g_K + ((size_t)bh * L_ + l0 + st * 128 + kr) * D_ + d4 * 4);
            KsT[(d4*4+0) * 129 + kr] = v.x; KsT[(d4*4+1) * 129 + kr] = v.y;
            KsT[(d4*4+2) * 129 + kr] = v.z; KsT[(d4*4+3) * 129 + kr] = v.w;
        }
        __syncthreads();
        float acc[14];
#pragma unroll
        for (int i = 0; i < 14; i++) acc[i] = 0.f;
#pragma unroll
        for (int d0 = 0; d0 < 64; d0 += 4) {
            float k0 = KsT[d0*129 + kk], k1 = KsT[(d0+1)*129 + kk];
            float k2 = KsT[(d0+2)*129 + kk], k3 = KsT[(d0+3)*129 + kk];
#pragma unroll
            for (int i = 0; i < 14; i++) {
                if (i < ucnt) {
                    float4 q = *(const float4*)&sQ[(ubeg + i) * 64 + d0];
                    acc[i] += q.x*k0 + q.y*k1 + q.z*k2 + q.w*k3;
                }
            }
        }
#pragma unroll
        for (int i = 0; i < 14; i++)
            if (i < ucnt) sS[(ubeg + i) * CH + st * 128 + kk] = acc[i] * 0.125f;
    }
    __syncthreads();

    for (int u = w; u < NS_; u += 8) {
        float mx = -__int_as_float(0x7f800000);
#pragma unroll
        for (int j = 0; j < CH / 32; j++)
            mx = fmaxf(mx, sS[u * CH + lane + j * 32]);
#pragma unroll
        for (int off = 16; off > 0; off >>= 1)
            mx = fmaxf(mx, __shfl_xor_sync(0xffffffffu, mx, off));
        float ss = 0.f;
#pragma unroll
        for (int j = 0; j < CH / 32; j++) {
            float e = __expf(sS[u * CH + lane + j * 32] - mx);
            sS[u * CH + lane + j * 32] = e;
            ss += e;
        }
#pragma unroll
        for (int off = 16; off > 0; off >>= 1)
            ss += __shfl_xor_sync(0xffffffffu, ss, off);
        if (lane == 0) {
            int pi = (bh * NCH + ch) * NS_ + u;
            g_attM[pi] = mx;
            g_attS[pi] = ss;
        }
    }
    __syncthreads();

    int d = t & 63, ug = t >> 6;
    float acc[7];
#pragma unroll
    for (int j = 0; j < 7; j++) acc[j] = 0.f;
    for (int k = 0; k < CH; k += 4) {
        float v0 = g_V[((size_t)bh * L_ + l0 + k + 0) * D_ + d];
        float v1 = g_V[((size_t)bh * L_ + l0 + k + 1) * D_ + d];
        float v2 = g_V[((size_t)bh * L_ + l0 + k + 2) * D_ + d];
        float v3 = g_V[((size_t)bh * L_ + l0 + k + 3) * D_ + d];
#pragma unroll
        for (int j = 0; j < 7; j++) {
            int u = ug + j * 4;
            if (u < NS_) {
                float4 p = *(const float4*)&sS[u * CH + k];
                acc[j] += p.x*v0 + p.y*v1 + p.z*v2 + p.w*v3;
            }
        }
    }
#pragma unroll
    for (int j = 0; j < 7; j++) {
        int u = ug + j * 4;
        if (u < NS_)
            g_attO[((size_t)(bh * NCH + ch) * NS_ + u) * D_ + d] = acc[j];
    }
}

// ---------------- layer-1 attention over low-rank K1/V1 ----------------
__global__ __launch_bounds__(256)
void att1_fused_kernel() {
    __shared__ float sQ[64];
    __shared__ float sS[SLOTS];
    __shared__ float red[256];
    __shared__ float sstat[2];
    int bu = blockIdx.x;
    int bh = bu / NS_, u = bu % NS_;
    int b = bh >> 3, h = bh & 7;
    int t = threadIdx.x;
    int cnt = g_cnt[b];
    int lsel = g_topidx[bh * NS_ + u];
    if (t < 64) sQ[t] = g_Q1[((size_t)bh * L_ + lsel) * D_ + t];
    __syncthreads();

    if (t < 32) {
        float p = sQ[t] * g_basekv[(size_t)b * DM_ + h * D_ + t]
                + sQ[t + 32] * g_basekv[(size_t)b * DM_ + h * D_ + t + 32];
#pragma unroll
        for (int off = 16; off > 0; off >>= 1)
            p += __shfl_xor_sync(0xffffffffu, p, off);
        if (t == 0) sstat[0] = 0.125f * p;
    }
    __syncthreads();
    float qb = sstat[0];

    float sj = -__int_as_float(0x7f800000);
    if (t < cnt) {
        const float4* c = (const float4*)(g_ck + ((size_t)(b * SLOTS + t)) * DM_ + h * D_);
        float dot = 0.f;
#pragma unroll
        for (int d4 = 0; d4 < 16; d4++) {
            float4 cv = c[d4];
            dot += sQ[d4*4]*cv.x + sQ[d4*4+1]*cv.y + sQ[d4*4+2]*cv.z + sQ[d4*4+3]*cv.w;
        }
        sj = qb + 0.125f * dot;
        sS[t] = sj;
    }
    red[t] = sj;
    __syncthreads();
    for (int s = 128; s > 0; s >>= 1) {
        if (t < s) red[t] = fmaxf(red[t], red[t + s]);
        __syncthreads();
    }
    float m = fmaxf(red[0], qb);
    __syncthreads();

    float e = 0.f;
    if (t < cnt) { e = __expf(sS[t] - m); sS[t] = e; }
    red[t] = e;
    __syncthreads();
    for (int s = 128; s > 0; s >>= 1) {
        if (t < s) red[t] += red[t + s];
        __syncthreads();
    }
    if (t == 0)
        sstat[1] = 1.f / (red[0] + (float)(L_ - cnt) * __expf(qb - m));
    __syncthreads();
    float inv = sstat[1];

    if (t < 64) {
        float o = 0.f;
        for (int j = 0; j < cnt; j++)
            o += sS[j] * g_ck[CKOFF + ((size_t)(b * SLOTS + j)) * DM_ + h * D_ + t];
        o = o * inv + g_basekv[(size_t)(B_ + b) * DM_ + h * D_ + t];
        g_outtop[(bh * NS_ + u) * D_ + t] = o;
    }
}

// ---------------- slot assignment ----------------
__global__ __launch_bounds__(256)
void slot_assign_kernel() {
    int b = blockIdx.x, t = threadIdx.x;
    __shared__ int cs[256];
    int base = t * 16;
    int c = 0;
#pragma unroll
    for (int i = 0; i < 16; i++)
        if (g_map[b * L_ + base + i] == 1) c++;
    cs[t] = c;
    __syncthreads();
    for (int off = 1; off < 256; off <<= 1) {
        int v = (t >= off) ? cs[t - off] : 0;
        __syncthreads();
        cs[t] += v;
        __syncthreads();
    }
    int slot = cs[t] - c;
#pragma unroll
    for (int i = 0; i < 16; i++) {
        if (g_map[b * L_ + base + i] == 1)
            g_map[b * L_ + base + i] = slot++;
    }
    if (t == 255) g_cnt[b] = cs[255];
}

__global__ __launch_bounds__(128)
void corr_compact_kernel() {
    int blk = blockIdx.x, z = blockIdx.y;
    int bh0 = blk / NS_, u = blk % NS_;
    int b = bh0 >> 3, h0 = bh0 & 7;
    int t = threadIdx.x;
    __shared__ float qv[64];
    if (t < 64) qv[t] = g_outtop[(bh0 * NS_ + u) * 64 + t] - g_meanV[bh0 * 64 + t];
    __syncthreads();
    const float* T = g_Tkv + (size_t)z * DM_ * DM_;
    int l = g_topidx[bh0 * NS_ + u];
    int slot = g_map[b * L_ + l];
    float a0 = 0.f, a1 = 0.f, a2 = 0.f, a3 = 0.f;
#pragma unroll 8
    for (int k = 0; k < 64; k++) {
        float q = qv[k];
        float4 wv = *(const float4*)(T + (size_t)(h0 * 64 + k) * DM_ + t * 4);
        a0 += q * wv.x; a1 += q * wv.y; a2 += q * wv.z; a3 += q * wv.w;
    }
    float* dst = g_ck + (size_t)z * CKOFF + ((size_t)(b * SLOTS + slot)) * DM_ + t * 4;
    atomicAdd(dst + 0, a0); atomicAdd(dst + 1, a1);
    atomicAdd(dst + 2, a2); atomicAdd(dst + 3, a3);
}

// ---------------- generic GEMV: partials then combine ----------------
__global__ __launch_bounds__(512)
void base1g_kernel(const float* __restrict__ invec, const float* __restrict__ w) {
    int b = blockIdx.x, kc = blockIdx.y, n = threadIdx.x;
    __shared__ float mc[64];
    if (n < 64) mc[n] = invec[b * DM_ + kc * 64 + n];
    __syncthreads();
    float s = 0.f;
#pragma unroll 8
    for (int k = 0; k < 64; k++) s += mc[k] * w[(size_t)(kc * 64 + k) * DM_ + n];
    g_basep[(b * 8 + kc) * DM_ + n] = s;
}

__global__ __launch_bounds__(512)
void base2g_kernel(const float* __restrict__ bias, float* __restrict__ outv) {
    int b = blockIdx.x, n = threadIdx.x;
    float s = bias[n];
#pragma unroll
    for (int p = 0; p < 8; p++) s += g_basep[(b * 8 + p) * DM_ + n];
    outv[b * DM_ + n] = s;
}

struct KV2 { const float* w[2]; const float* bias[2]; };
__global__ __launch_bounds__(512)
void basekv1_kernel(const float* __restrict__ invec, KV2 kv) {
    int b = blockIdx.x, kc = blockIdx.y, z = blockIdx.z, n = threadIdx.x;
    __shared__ float mc[64];
    if (n < 64) mc[n] = invec[b * DM_ + kc * 64 + n];
    __syncthreads();
    const float* w = kv.w[z];
    float s = 0.f;
#pragma unroll 8
    for (int k = 0; k < 64; k++) s += mc[k] * w[(size_t)(kc * 64 + k) * DM_ + n];
    g_basep2[((z * B_ + b) * 8 + kc) * DM_ + n] = s;
}

__global__ __launch_bounds__(512)
void basekv2_kernel(KV2 kv) {
    int b = blockIdx.x, z = blockIdx.y, n = threadIdx.x;
    float s = kv.bias[z][n];
#pragma unroll
    for (int p = 0; p < 8; p++) s += g_basep2[((z * B_ + b) * 8 + p) * DM_ + n];
    g_basekv[(z * B_ + b) * DM_ + n] = s;
}

// ---------------- output broadcasts ----------------
__global__ __launch_bounds__(256)
void bcast_out_kernel(const float* __restrict__ xs, float* __restrict__ out,
                      const float* __restrict__ basev, int row_off) {
    int i4 = blockIdx.x * 256 + threadIdx.x;
    int n4 = i4 & 127;
    int l = (i4 >> 7) & 4095;
    int b = i4 / (L_ * 128);
    size_t oi = ((size_t)(b * 8192 + row_off + l)) * 128 + n4;
    float4 a = ((const float4*)xs)[oi];
    float4 s = ((const float4*)basev)[b * 128 + n4];
    a.x += s.x; a.y += s.y; a.z += s.z; a.w += s.w;
    ((float4*)out)[oi] = a;
}

__global__ __launch_bounds__(128)
void corr_kernel(const float* __restrict__ wo, float* __restrict__ dst, int row_off) {
    int blk = blockIdx.x;
    int bh = blk / NS_, u = blk % NS_;
    int b = bh >> 3, h = bh & 7;
    int t = threadIdx.x;
    __shared__ float qv[64];
    if (t < 64) qv[t] = g_outtop[(bh * NS_ + u) * 64 + t] - g_meanV[bh * 64 + t];
    __syncthreads();
    int l = g_topidx[bh * NS_ + u];
    float a0 = 0.f, a1 = 0.f, a2 = 0.f, a3 = 0.f;
#pragma unroll 8
    for (int k = 0; k < 64; k++) {
        float q = qv[k];
        float4 wv = *(const float4*)(wo + (size_t)(h * 64 + k) * DM_ + t * 4);
        a0 += q * wv.x; a1 += q * wv.y; a2 += q * wv.z; a3 += q * wv.w;
    }
    float* d = dst + ((size_t)(b * 8192 + row_off + l)) * DM_ + t * 4;
    atomicAdd(d + 0, a0); atomicAdd(d + 1, a1);
    atomicAdd(d + 2, a2); atomicAdd(d + 3, a3);
}

// ---------------- host orchestration ----------------
extern "C" void kernel_launch(void* const* d_in, const int* in_sizes, int n_in,
                              void* d_out, int out_size) {
    const float* xs  = (const float*)d_in[0];
    const float* xd  = (const float*)d_in[1];
    const float* xp  = (const float*)d_in[2];
    const float* w0q = (const float*)d_in[3];
    const float* w0k = (const float*)d_in[4];
    const float* w0v = (const float*)d_in[5];
    const float* w0o = (const float*)d_in[6];
    const float* b0q = (const float*)d_in[7];
    const float* b0k = (const float*)d_in[8];
    const float* b0v = (const float*)d_in[9];
    const float* b0o = (const float*)d_in[10];
    const float* w1q = (const float*)d_in[11];
    const float* w1k = (const float*)d_in[12];
    const float* w1v = (const float*)d_in[13];
    const float* w1o = (const float*)d_in[14];
    const float* b1q = (const float*)d_in[15];
    const float* b1k = (const float*)d_in[16];
    const float* b1v = (const float*)d_in[17];
    const float* b1o = (const float*)d_in[18];
    float* out = (float*)d_out;

    float *pQ, *pQ1, *pK, *pV, *pmv, *pb0, *pb1, *pck, *pTkv;
    int *pidxA, *pidxB, *pmap;
    __nv_bfloat16 *pAxdH, *pAxdL, *pAxpH, *pAxpL, *pWtH, *pWtL;
    cudaGetSymbolAddress((void**)&pQ, g_Q);
    cudaGetSymbolAddress((void**)&pQ1, g_Q1);
    cudaGetSymbolAddress((void**)&pK, g_K);
    cudaGetSymbolAddress((void**)&pV, g_V);
    cudaGetSymbolAddress((void**)&pmv, g_meanV);
    cudaGetSymbolAddress((void**)&pb0, g_base0);
    cudaGetSymbolAddress((void**)&pb1, g_base1);
    cudaGetSymbolAddress((void**)&pck, g_ck);
    cudaGetSymbolAddress((void**)&pTkv, g_Tkv);
    cudaGetSymbolAddress((void**)&pmap, g_map);
    cudaGetSymbolAddress((void**)&pidxA, g_idxA);
    cudaGetSymbolAddress((void**)&pidxB, g_idxB);
    cudaGetSymbolAddress((void**)&pAxdH, g_Axd_hi);
    cudaGetSymbolAddress((void**)&pAxdL, g_Axd_lo);
    cudaGetSymbolAddress((void**)&pAxpH, g_Axp_hi);
    cudaGetSymbolAddress((void**)&pAxpL, g_Axp_lo);
    cudaGetSymbolAddress((void**)&pWtH, g_Wt_hi);
    cudaGetSymbolAddress((void**)&pWtL, g_Wt_lo);

    cudaFuncSetAttribute(gemm_mma4, cudaFuncAttributeMaxDynamicSharedMemorySize, GSMEM);
    cudaFuncSetAttribute(att_fused_kernel, cudaFuncAttributeMaxDynamicSharedMemorySize, ATT_SMEM);

    // scratch init
    cudaMemsetAsync(pmap, 0xFF, (size_t)B_ * L_ * sizeof(int));
    cudaMemsetAsync(pck, 0, (size_t)2 * B_ * SLOTS * DM_ * sizeof(float));
    cudaMemsetAsync(pTkv, 0, (size_t)2 * DM_ * DM_ * sizeof(float));

    // idx tables
    {
        unsigned a42, b42, a43, b43;
        tf2x32(0u, 42u, 0u, 1u, &a42, &b42);
        tf2x32(0u, 43u, 0u, 1u, &a43, &b43);
        IdxKeys ik;
        ik.k0[0] = a42; ik.k1[0] = b42; ik.out[0] = pidxA;
        ik.k0[1] = a43; ik.k1[1] = b43; ik.out[1] = pidxB;
        idx2_kernel<<<dim3((L_ * NS_ + 255) / 256, 2), 256>>>(ik);
    }

    W4 ws;
    ws.w[0] = w0q; ws.w[1] = w0k; ws.w[2] = w0v; ws.w[3] = w1q;
    wt_cvt_all_kernel<<<dim3(16, 16, 4), dim3(32, 32)>>>(ws, pWtH, pWtL);

    // T = Wo0 @ W1{k,v}: split-K with direct atomic accumulation
    TW tw; tw.b[0] = w1k; tw.b[1] = w1v;
    sgemm_T_part<<<dim3(8, 8, 32), 256>>>(w0o, tw);

    const int N4 = BL_ * DM_ / 4;     // 2097152
    const int N4Q = N4 / 4;           // 524288
    {
        Cvt2 c;
        c.src[0] = (const float4*)xd; c.src[1] = (const float4*)xp;
        c.hi[0] = (__nv_bfloat162*)pAxdH; c.hi[1] = (__nv_bfloat162*)pAxpH;
        c.lo[0] = (__nv_bfloat162*)pAxdL; c.lo[1] = (__nv_bfloat162*)pAxpL;
        cvt_pair2_kernel<<<dim3(N4Q / 256, 2), 256>>>(c, N4Q);
    }

    // ---- ALL 4 dense GEMMs in one launch (Q0, K0, V0, Q1) ----
    {
        G4 g4;
        size_t WS = (size_t)DM_ * DM_;
        g4.j[0].ahi = pAxpH; g4.j[0].alo = pAxpL; g4.j[0].bhi = pWtH + 0*WS; g4.j[0].blo = pWtL + 0*WS; g4.j[0].bias = b0q; g4.j[0].c = pQ;
        g4.j[1].ahi = pAxdH; g4.j[1].alo = pAxdL; g4.j[1].bhi = pWtH + 1*WS; g4.j[1].blo = pWtL + 1*WS; g4.j[1].bias = b0k; g4.j[1].c = pK;
        g4.j[2].ahi = pAxdH; g4.j[2].alo = pAxdL; g4.j[2].bhi = pWtH + 2*WS; g4.j[2].blo = pWtL + 2*WS; g4.j[2].bias = b0v; g4.j[2].c = pV;
        g4.j[3].ahi = pAxdH; g4.j[3].alo = pAxdL; g4.j[3].bhi = pWtH + 3*WS; g4.j[3].blo = pWtL + 3*WS; g4.j[3].bias = b1q; g4.j[3].c = pQ1;
        gemm_mma4<<<dim3(DM_ / 128, BL_ / 128, 4), 256, GSMEM>>>(g4);
    }

    // ---- layer 0 attention ----
    sample_m_kernel<<<(BH_ * L_) / 8, 256>>>(pidxA);
    topk_kernel<<<BH_, 256>>>(1);         // also marks g_map
    meanv1_kernel<<<dim3(BH_, 16), 256>>>();
    att_fused_kernel<<<dim3(BH_, NCH), 256, ATT_SMEM>>>();
    combine2_kernel<<<BH_ * NS_ + BH_, 64>>>();   // att_combine + meanv2

    // base0 = meanctx0 @ Wo0 + bo0
    base1g_kernel<<<dim3(B_, 8), 512>>>(pmv, w0o);
    base2g_kernel<<<B_, 512>>>(b0o, pb0);

    // output upper half (xp2)
    bcast_out_kernel<<<(B_ * L_ * 128) / 256, 256>>>(xs, out, pb0, 4096);
    corr_kernel<<<BH_ * NS_, 128>>>(w0o, out, 4096);

    // ---- compact low-rank K1/V1 ----
    slot_assign_kernel<<<B_, 256>>>();
    corr_compact_kernel<<<dim3(BH_ * NS_, 2), 128>>>();
    {
        KV2 kv;
        kv.w[0] = w1k; kv.w[1] = w1v;
        kv.bias[0] = b1k; kv.bias[1] = b1v;
        basekv1_kernel<<<dim3(B_, 8, 2), 512>>>(pb0, kv);
        basekv2_kernel<<<dim3(B_, 2), 512>>>(kv);
    }

    // ---- layer 1 attention (low-rank K1/V1, Q from g_Q1) ----
    sample_m1_kernel<<<(BH_ * L_) / 8, 256>>>(pidxB);
    topk_kernel<<<BH_, 256>>>(0);
    meanv1b_kernel<<<BH_, 64>>>();
    att1_fused_kernel<<<BH_ * NS_, 256>>>();

    // base1 + output lower half (xd2)
    base1g_kernel<<<dim3(B_, 8), 512>>>(pmv, w1o);
    base2g_kernel<<<B_, 512>>>(b1o, pb1);
    bcast_out_kernel<<<(B_ * L_ * 128) / 256, 256>>>(xs, out, pb1, 0);
    corr_kernel<<<BH_ * NS_, 128>>>(w1o, out, 0);
}

// round 17
// speedup vs baseline: 1.1604x; 1.1381x over previous
#include <cuda_runtime.h>
#include <cuda_bf16.h>
#include <math.h>
#include <stdint.h>

#define B_   4
#define H_   8
#define L_   4096
#define D_   64
#define DM_  512
#define NS_  27
#define BH_  (B_*H_)
#define BL_  (B_*L_)
#define NCH  8
#define CH   (L_/NCH)   // 512
#define SLOTS 216
#define CKOFF ((size_t)B_*SLOTS*DM_)

// ---------------- scratch (device globals; no runtime alloc) ----------------
__device__ float g_Q[BH_*L_*D_];
__device__ float g_Q1[BH_*L_*D_];
__device__ float g_K[BH_*L_*D_];
__device__ float g_V[BH_*L_*D_];
__device__ float g_M[BH_*L_];
__device__ float g_outtop[BH_*NS_*D_];
__device__ float g_meanV[BH_*D_];
__device__ float g_vpart[BH_*16*D_];
__device__ float g_attM[BH_*NCH*NS_];
__device__ float g_attS[BH_*NCH*NS_];
__device__ float g_attO[BH_*NCH*NS_*D_];
__device__ float g_base0[B_*DM_];
__device__ float g_base1[B_*DM_];
__device__ float g_basekv[2*B_*DM_];
__device__ float g_basep[B_*8*DM_];
__device__ float g_basep2[2*B_*8*DM_];
__device__ float g_Tkv[2*DM_*DM_];
__device__ float g_ck[2*B_*SLOTS*DM_];     // [0]=K corrections, [CKOFF]=V corrections
__device__ int   g_map[B_*L_];
__device__ int   g_cnt[B_];
__device__ int   g_idxA[L_*NS_];
__device__ int   g_idxB[L_*NS_];
__device__ int   g_topidx[BH_*NS_];

// bf16-split operand buffers
__device__ __nv_bfloat16 g_Axd_hi[(size_t)BL_*DM_];
__device__ __nv_bfloat16 g_Axd_lo[(size_t)BL_*DM_];
__device__ __nv_bfloat16 g_Axp_hi[(size_t)BL_*DM_];
__device__ __nv_bfloat16 g_Axp_lo[(size_t)BL_*DM_];
__device__ __nv_bfloat16 g_Wt_hi[4*DM_*DM_];   // w0q, w0k, w0v, w1q
__device__ __nv_bfloat16 g_Wt_lo[4*DM_*DM_];

// ---------------- Threefry-2x32 (JAX-exact) ----------------
__host__ __device__ __forceinline__ void tf2x32(unsigned k0, unsigned k1,
                                                unsigned x0, unsigned x1,
                                                unsigned* o0, unsigned* o1) {
    unsigned ks0 = k0, ks1 = k1, ks2 = 0x1BD11BDAu ^ k0 ^ k1;
    x0 += ks0; x1 += ks1;
#define TF_RND(r) { x0 += x1; x1 = (x1 << (r)) | (x1 >> (32 - (r))); x1 ^= x0; }
    TF_RND(13) TF_RND(15) TF_RND(26) TF_RND(6)   x0 += ks1; x1 += ks2 + 1u;
    TF_RND(17) TF_RND(29) TF_RND(16) TF_RND(24)  x0 += ks2; x1 += ks0 + 2u;
    TF_RND(13) TF_RND(15) TF_RND(26) TF_RND(6)   x0 += ks0; x1 += ks1 + 3u;
    TF_RND(17) TF_RND(29) TF_RND(16) TF_RND(24)  x0 += ks1; x1 += ks2 + 4u;
    TF_RND(13) TF_RND(15) TF_RND(26) TF_RND(6)   x0 += ks2; x1 += ks0 + 5u;
#undef TF_RND
    *o0 = x0; *o1 = x1;
}

struct IdxKeys { unsigned k0[2], k1[2]; int* out[2]; };
__global__ void idx2_kernel(IdxKeys ik) {
    int i = blockIdx.x * blockDim.x + threadIdx.x;
    if (i >= L_*NS_) return;
    int z = blockIdx.y;
    unsigned o0, o1;
    tf2x32(ik.k0[z], ik.k1[z], 0u, (unsigned)i, &o0, &o1);
    ik.out[z][i] = (int)((o0 ^ o1) & 4095u);
}

// ---------------- bf16-split conversion (MLP=4, both inputs one launch) ----
struct Cvt2 { const float4* src[2]; __nv_bfloat162* hi[2]; __nv_bfloat162* lo[2]; };
__global__ __launch_bounds__(256)
void cvt_pair2_kernel(Cvt2 c, int n4q) {   // n4q = N4/4
    int z = blockIdx.y;
    int i = blockIdx.x * 256 + threadIdx.x;
    if (i >= n4q) return;
    const float4* __restrict__ src = c.src[z];
    __nv_bfloat162* __restrict__ hi = c.hi[z];
    __nv_bfloat162* __restrict__ lo = c.lo[z];
    float4 v[4];
#pragma unroll
    for (int j = 0; j < 4; j++) v[j] = src[i + j * n4q];
#pragma unroll
    for (int j = 0; j < 4; j++) {
        int ii = i + j * n4q;
        float4 w = v[j];
        __nv_bfloat16 h0 = __float2bfloat16(w.x), h1 = __float2bfloat16(w.y);
        __nv_bfloat16 h2 = __float2bfloat16(w.z), h3 = __float2bfloat16(w.w);
        __nv_bfloat16 l0 = __float2bfloat16(w.x - __bfloat162float(h0));
        __nv_bfloat16 l1 = __float2bfloat16(w.y - __bfloat162float(h1));
        __nv_bfloat16 l2 = __float2bfloat16(w.z - __bfloat162float(h2));
        __nv_bfloat16 l3 = __float2bfloat16(w.w - __bfloat162float(h3));
        hi[ii*2]   = __nv_bfloat162(h0, h1);
        hi[ii*2+1] = __nv_bfloat162(h2, h3);
        lo[ii*2]   = __nv_bfloat162(l0, l1);
        lo[ii*2+1] = __nv_bfloat162(l2, l3);
    }
}

struct W4 { const float* w[4]; };
__global__ __launch_bounds__(1024)
void wt_cvt_all_kernel(W4 ws, __nv_bfloat16* __restrict__ hi, __nv_bfloat16* __restrict__ lo) {
    __shared__ float t[32][33];
    int tx = threadIdx.x, ty = threadIdx.y;
    int n0 = blockIdx.x * 32, k0 = blockIdx.y * 32;
    int z = blockIdx.z;
    const float* W = ws.w[z];
    size_t off = (size_t)z * DM_ * DM_;
    t[ty][tx] = W[(size_t)(k0 + ty) * DM_ + n0 + tx];
    __syncthreads();
    float v = t[tx][ty];
    int n = n0 + ty, k = k0 + tx;
    __nv_bfloat16 h = __float2bfloat16(v);
    hi[off + (size_t)n * DM_ + k] = h;
    lo[off + (size_t)n * DM_ + k] = __float2bfloat16(v - __bfloat162float(h));
}

// ---------------- PTX helpers ----------------
__device__ __forceinline__ void cp16s(uint32_t saddr, const void* g) {
    asm volatile("cp.async.cg.shared.global [%0], [%1], 16;\n" :: "r"(saddr), "l"(g));
}
#define CP_COMMIT() asm volatile("cp.async.commit_group;\n" ::: "memory")
#define CP_WAIT(n)  asm volatile("cp.async.wait_group %0;\n" :: "n"(n) : "memory")

__device__ __forceinline__ void ldsm4(uint32_t& r0, uint32_t& r1, uint32_t& r2, uint32_t& r3,
                                      uint32_t saddr) {
    asm volatile("ldmatrix.sync.aligned.m8n8.x4.shared.b16 {%0,%1,%2,%3}, [%4];"
                 : "=r"(r0), "=r"(r1), "=r"(r2), "=r"(r3) : "r"(saddr));
}

__device__ __forceinline__ void mma_bf16(float* c, const uint32_t* a, const uint32_t* b) {
    asm volatile("mma.sync.aligned.m16n8k16.row.col.f32.bf16.bf16.f32 "
                 "{%0,%1,%2,%3}, {%4,%5,%6,%7}, {%8,%9}, {%0,%1,%2,%3};"
                 : "+f"(c[0]), "+f"(c[1]), "+f"(c[2]), "+f"(c[3])
                 : "r"(a[0]), "r"(a[1]), "r"(a[2]), "r"(a[3]), "r"(b[0]), "r"(b[1]));
}

// ---------------- mma.sync bf16-split GEMM (BK=32, 2-stage, 2 CTAs/SM) -----
#define GST    40960
#define GSMEM  (2048 + 2*GST)

struct GJob { const __nv_bfloat16 *ahi, *alo, *bhi, *blo; const float* bias; float* c; };
struct G4 { GJob j[4]; };

__global__ __launch_bounds__(256, 2)
void gemm_mma4(G4 g4) {
    extern __shared__ char smem[];
    const uint32_t sb = (uint32_t)__cvta_generic_to_shared(smem);
    const int tid = threadIdx.x;
    const int lane = tid & 31, wid = tid >> 5;
    const int warpM = wid >> 2, warpN = wid & 3;
    const int row0 = blockIdx.y * 128, col0 = blockIdx.x * 128;
    GJob jb = g4.j[blockIdx.z];
    const __nv_bfloat16* __restrict__ Ahi = jb.ahi;
    const __nv_bfloat16* __restrict__ Alo = jb.alo;
    const __nv_bfloat16* __restrict__ Bhi = jb.bhi;
    const __nv_bfloat16* __restrict__ Blo = jb.blo;

    float* sbias = (float*)smem;
    if (tid < 128) sbias[tid] = jb.bias[col0 + tid];

    float acc[4][4][4];
#pragma unroll
    for (int i = 0; i < 4; i++)
#pragma unroll
        for (int j = 0; j < 4; j++)
#pragma unroll
            for (int r = 0; r < 4; r++) acc[i][j][r] = 0.f;

    const int a_row = warpM * 64 + (lane & 15);
    const int a_kb  = ((lane >> 4) * 8) * 2;
    const int b_row = warpN * 32 + (lane & 7) + ((lane >> 4) & 1) * 8;
    const int b_kb  = (((lane >> 3) & 1) * 8) * 2;

#define LOAD_CHUNK(c, s) {                                                     \
    uint32_t stb = sb + 2048 + (uint32_t)(s) * GST;                            \
    int k0 = (c) * 32;                                                         \
    _Pragma("unroll")                                                          \
    for (int j = 0; j < 8; j++) {                                              \
        int idx = tid + j * 256;                                               \
        int tile = idx >> 9, w = idx & 511;                                    \
        int r = w >> 2, cc = w & 3;                                            \
        uint32_t so = stb + (uint32_t)tile * 10240u + (uint32_t)(r * 80 + cc * 16); \
        const __nv_bfloat16* gp;                                               \
        if      (tile == 0) gp = Ahi + (size_t)(row0 + r) * DM_ + k0 + cc * 8; \
        else if (tile == 1) gp = Alo + (size_t)(row0 + r) * DM_ + k0 + cc * 8; \
        else if (tile == 2) gp = Bhi + (size_t)(col0 + r) * DM_ + k0 + cc * 8; \
        else                gp = Blo + (size_t)(col0 + r) * DM_ + k0 + cc * 8; \
        cp16s(so, gp);                                                         \
    }                                                                          \
    CP_COMMIT(); }

#define COMPUTE(s) {                                                                 \
    uint32_t stb = sb + 2048 + (uint32_t)(s) * GST;                                  \
    _Pragma("unroll")                                                                \
    for (int k16 = 0; k16 < 2; k16++) {                                             \
        uint32_t ah[4][4], al[4][4], bh[4][2], bl[4][2];                             \
        _Pragma("unroll")                                                            \
        for (int i = 0; i < 4; i++)                                                  \
            ldsm4(ah[i][0], ah[i][1], ah[i][2], ah[i][3],                            \
                  stb + (uint32_t)((a_row + i*16) * 80 + k16*32 + a_kb));            \
        _Pragma("unroll")                                                            \
        for (int n16 = 0; n16 < 2; n16++)                                            \
            ldsm4(bh[n16*2][0], bh[n16*2][1], bh[n16*2+1][0], bh[n16*2+1][1],        \
                  stb + 20480u + (uint32_t)((b_row + n16*16) * 80 + k16*32 + b_kb)); \
        _Pragma("unroll")                                                            \
        for (int i = 0; i < 4; i++)                                                  \
            _Pragma("unroll")                                                        \
            for (int j = 0; j < 4; j++) mma_bf16(acc[i][j], ah[i], bh[j]);           \
        _Pragma("unroll")                                                            \
        for (int n16 = 0; n16 < 2; n16++)                                            \
            ldsm4(bl[n16*2][0], bl[n16*2][1], bl[n16*2+1][0], bl[n16*2+1][1],        \
                  stb + 30720u + (uint32_t)((b_row + n16*16) * 80 + k16*32 + b_kb)); \
        _Pragma("unroll")                                                            \
        for (int i = 0; i < 4; i++)                                                  \
            _Pragma("unroll")                                                        \
            for (int j = 0; j < 4; j++) mma_bf16(acc[i][j], ah[i], bl[j]);           \
        _Pragma("unroll")                                                            \
        for (int i = 0; i < 4; i++)                                                  \
            ldsm4(al[i][0], al[i][1], al[i][2], al[i][3],                            \
                  stb + 10240u + (uint32_t)((a_row + i*16) * 80 + k16*32 + a_kb));   \
        _Pragma("unroll")                                                            \
        for (int i = 0; i < 4; i++)                                                  \
            _Pragma("unroll")                                                        \
            for (int j = 0; j < 4; j++) mma_bf16(acc[i][j], al[i], bh[j]);           \
    } }

    LOAD_CHUNK(0, 0);
    LOAD_CHUNK(1, 1);

    const int nIter = DM_ / 32;   // 16
#pragma unroll 1
    for (int c = 0; c < nIter; c++) {
        if (c == nIter - 1) { CP_WAIT(0); } else { CP_WAIT(1); }
        __syncthreads();
        COMPUTE(c & 1);
        __syncthreads();
        if (c + 2 < nIter) LOAD_CHUNK(c + 2, c & 1);
    }

    __syncthreads();
#pragma unroll
    for (int i = 0; i < 4; i++) {
#pragma unroll
        for (int j = 0; j < 4; j++) {
            int colg = col0 + warpN * 32 + j * 8 + (lane & 3) * 2;
            int hh = colg >> 6, d0 = colg & 63;
            float b0v = sbias[colg - col0], b1v = sbias[colg - col0 + 1];
#pragma unroll
            for (int half = 0; half < 2; half++) {
                int m = row0 + warpM * 64 + i * 16 + (lane >> 2) + half * 8;
                int b = m >> 12, l = m & 4095;
                float2 v;
                v.x = acc[i][j][half*2 + 0] + b0v;
                v.y = acc[i][j][half*2 + 1] + b1v;
                *(float2*)(jb.c + (((size_t)(b * H_ + hh) * L_) + l) * D_ + d0) = v;
            }
        }
    }
#undef LOAD_CHUNK
#undef COMPUTE
}

// ------- T GEMMs: split-K, atomic accumulate directly into g_Tkv -------
struct TW { const float* b[2]; };
__global__ __launch_bounds__(256)
void sgemm_T_part(const float* __restrict__ A, TW tw) {
    __shared__ float As[16][68];
    __shared__ float Bs[16][64];
    int tid = threadIdx.x, tx = tid & 15, ty = tid >> 4;
    int r0 = blockIdx.y * 64, c0 = blockIdx.x * 64;
    int kc = blockIdx.z & 15, which = blockIdx.z >> 4;
    const float* Bm = tw.b[which];
    float acc[4][4];
#pragma unroll
    for (int i = 0; i < 4; i++)
#pragma unroll
        for (int j = 0; j < 4; j++) acc[i][j] = 0.f;

    for (int kt = kc * 32; kt < kc * 32 + 32; kt += 16) {
        int m = tid >> 2, k4 = tid & 3;
        float4 av = *(const float4*)(A + (size_t)(r0 + m) * DM_ + kt + k4 * 4);
        As[k4*4+0][m] = av.x; As[k4*4+1][m] = av.y;
        As[k4*4+2][m] = av.z; As[k4*4+3][m] = av.w;
        int kk = tid >> 4, n4 = tid & 15;
        *(float4*)&Bs[kk][n4 * 4] = *(const float4*)(Bm + (size_t)(kt + kk) * DM_ + c0 + n4 * 4);
        __syncthreads();
#pragma unroll
        for (int k = 0; k < 16; k++) {
            float a[4], b[4];
            *(float4*)a = *(const float4*)&As[k][ty * 4];
            *(float4*)b = *(const float4*)&Bs[k][tx * 4];
#pragma unroll
            for (int i = 0; i < 4; i++)
#pragma unroll
                for (int j = 0; j < 4; j++) acc[i][j] += a[i] * b[j];
        }
        __syncthreads();
    }
    float* dst = g_Tkv + (size_t)which * DM_ * DM_ + (size_t)(r0 + ty * 4) * DM_ + c0 + tx * 4;
#pragma unroll
    for (int i = 0; i < 4; i++) {
        atomicAdd(dst + (size_t)i * DM_ + 0, acc[i][0]);
        atomicAdd(dst + (size_t)i * DM_ + 1, acc[i][1]);
        atomicAdd(dst + (size_t)i * DM_ + 2, acc[i][2]);
        atomicAdd(dst + (size_t)i * DM_ + 3, acc[i][3]);
    }
}

// ---------------- layer-0 sample_m (dense K, coalesced row loads) ----------
__global__ __launch_bounds__(256)
void sample_m_kernel(const int* __restrict__ idx) {
    int gw = (blockIdx.x * blockDim.x + threadIdx.x) >> 5;
    int lane = threadIdx.x & 31;
    if (gw >= BH_ * L_) return;
    int bh = gw >> 12, l = gw & 4095;
    const float2 q = ((const float2*)(g_Q + ((size_t)bh * L_ + l) * D_))[lane];
    int myidx = (lane < NS_) ? idx[l * NS_ + lane] : 0;
    const float* Kb = g_K + (size_t)bh * L_ * D_;
    float mx = -__int_as_float(0x7f800000);
    float sm = 0.f;
#pragma unroll 3
    for (int s = 0; s < NS_; s++) {
        int kk = __shfl_sync(0xffffffffu, myidx, s);
        float2 k = ((const float2*)(Kb + (size_t)kk * D_))[lane];
        float p = q.x * k.x + q.y * k.y;
#pragma unroll
        for (int off = 16; off > 0; off >>= 1)
            p += __shfl_xor_sync(0xffffffffu, p, off);
        mx = fmaxf(mx, p);
        sm += p;
    }
    if (lane == 0) g_M[gw] = mx - sm * (1.f / (float)L_);
}

// ---------------- layer-1 sample_m (low-rank K1, idx table) ----------------
__global__ __launch_bounds__(256)
void sample_m1_kernel(const int* __restrict__ idx) {
    int gw = (blockIdx.x * blockDim.x + threadIdx.x) >> 5;
    int lane = threadIdx.x & 31;
    if (gw >= BH_ * L_) return;
    int bh = gw >> 12, l = gw & 4095;
    int b = bh >> 3, h = bh & 7;
    const float4* qrow = (const float4*)(g_Q1 + ((size_t)bh * L_ + l) * D_);
    const float4* brow = (const float4*)(g_basekv + (size_t)b * DM_ + h * D_);
    bool active = lane < NS_;
    int j = -1;
    if (active) {
        int kk = idx[l * NS_ + lane];
        j = g_map[b * L_ + kk];
    }
    float s = 0.f;
#pragma unroll
    for (int d4 = 0; d4 < 16; d4++) {
        float4 q = qrow[d4], bb = brow[d4];
        s += q.x*bb.x + q.y*bb.y + q.z*bb.z + q.w*bb.w;
    }
    if (j >= 0) {
        const float4* crow = (const float4*)(g_ck + ((size_t)(b * SLOTS + j)) * DM_ + h * D_);
#pragma unroll
        for (int d4 = 0; d4 < 16; d4++) {
            float4 q = qrow[d4], c = crow[d4];
            s += q.x*c.x + q.y*c.y + q.z*c.z + q.w*c.w;
        }
    }
    float val = s;
    float mx = active ? val : -__int_as_float(0x7f800000);
    float sm = active ? val : 0.f;
#pragma unroll
    for (int off = 16; off > 0; off >>= 1) {
        mx = fmaxf(mx, __shfl_down_sync(0xffffffffu, mx, off));
        sm += __shfl_down_sync(0xffffffffu, sm, off);
    }
    if (lane == 0) g_M[gw] = mx - sm * (1.f / (float)L_);
}

// ---------------- top-27: cached per-thread max keys (+ optional mark) -----
__device__ __forceinline__ unsigned ordf(float v) {
    unsigned u = __float_as_uint(v);
    return (u & 0x80000000u) ? ~u : (u | 0x80000000u);
}

__global__ __launch_bounds__(256)
void topk_kernel(int domark) {
    int bh = blockIdx.x, t = threadIdx.x;
    int lane = t & 31, wid = t >> 5;
    __shared__ float sm[L_];
    __shared__ unsigned long long wred[8];
    __shared__ unsigned long long sbest;
    for (int i = t; i < L_; i += 256) sm[i] = g_M[(size_t)bh * L_ + i];
    __syncthreads();

    const int base = t * 16;
    unsigned long long myKey = 0ull;
#pragma unroll
    for (int i = 0; i < 16; i++) {
        unsigned long long key = ((unsigned long long)ordf(sm[base + i]) << 32)
                               | (unsigned)(L_ - 1 - (base + i));
        if (key > myKey) myKey = key;
    }

    int bB = bh >> 3;
    for (int it = 0; it < NS_; it++) {
        unsigned long long b = myKey;
#pragma unroll
        for (int off = 16; off > 0; off >>= 1) {
            unsigned long long o = __shfl_down_sync(0xffffffffu, b, off);
            if (o > b) b = o;
        }
        if (lane == 0) wred[wid] = b;
        __syncthreads();
        if (t == 0) {
            unsigned long long b2 = wred[0];
#pragma unroll
            for (int w = 1; w < 8; w++) if (wred[w] > b2) b2 = wred[w];
            sbest = b2;
            int idx = L_ - 1 - (int)(b2 & 0xFFFFFFFFull);
            g_topidx[bh * NS_ + it] = idx;
            if (domark) g_map[bB * L_ + idx] = 1;
        }
        __syncthreads();
        int gi = L_ - 1 - (int)(sbest & 0xFFFFFFFFull);
        if ((gi >> 4) == t) {
            sm[gi] = -__int_as_float(0x7f800000);
            unsigned long long nk = 0ull;
#pragma unroll
            for (int i = 0; i < 16; i++) {
                unsigned long long key = ((unsigned long long)ordf(sm[base + i]) << 32)
                                       | (unsigned)(L_ - 1 - (base + i));
                if (key > nk) nk = key;
            }
            myKey = nk;
        }
    }
}

// ---------------- layer-0 meanV: two-stage ----------------
__global__ __launch_bounds__(256)
void meanv1_kernel() {
    int bh = blockIdx.x, c = blockIdx.y, t = threadIdx.x;
    int d = t & 63, r = t >> 6;
    float s = 0.f;
    int base = c * 256;
    for (int l = base + r; l < base + 256; l += 4)
        s += g_V[((size_t)bh * L_ + l) * D_ + d];
    __shared__ float red[256];
    red[t] = s; __syncthreads();
    if (t < 64)
        g_vpart[(bh * 16 + c) * D_ + d] = red[d] + red[64+d] + red[128+d] + red[192+d];
}

// ---------------- merged meanv2 + att_combine (both 64-thread blocks) ------
__global__ __launch_bounds__(64)
void combine2_kernel() {
    int bid = blockIdx.x;
    int d = threadIdx.x;
    if (bid < BH_ * NS_) {
        int bh = bid / NS_, u = bid % NS_;
        float m = -__int_as_float(0x7f800000);
#pragma unroll
        for (int c = 0; c < NCH; c++)
            m = fmaxf(m, g_attM[(bh * NCH + c) * NS_ + u]);
        float s = 0.f, o = 0.f;
#pragma unroll
        for (int c = 0; c < NCH; c++) {
            int pi = (bh * NCH + c) * NS_ + u;
            float wgt = __expf(g_attM[pi] - m);
            s += wgt * g_attS[pi];
            o += wgt * g_attO[(size_t)pi * D_ + d];
        }
        g_outtop[(bh * NS_ + u) * D_ + d] = o / s;
    } else {
        int bh = bid - BH_ * NS_;
        float s = 0.f;
#pragma unroll
        for (int c = 0; c < 16; c++) s += g_vpart[(bh * 16 + c) * D_ + d];
        g_meanV[bh * D_ + d] = s * (1.f / (float)L_);
    }
}

// ---------------- layer-1 meanV (low-rank) ----------------
__global__ __launch_bounds__(64)
void meanv1b_kernel() {
    int bh = blockIdx.x, t = threadIdx.x;
    int b = bh >> 3, h = bh & 7;
    int cnt = g_cnt[b];
    float s = 0.f;
    for (int j = 0; j < cnt; j++)
        s += g_ck[CKOFF + ((size_t)(b * SLOTS + j)) * DM_ + h * D_ + t];
    g_meanV[bh * D_ + t] = g_basekv[(size_t)(B_ + b) * DM_ + h * D_ + t] + s * (1.f / (float)L_);
}

// ---------------- layer-0 fused scores+softmax+pv ----------------
#define ATT_SMEM ((NS_*CH + 64*129 + NS_*64 + 64) * 4)
__global__ __launch_bounds__(256, 2)
void att_fused_kernel() {
    extern __shared__ float smf[];
    float* sS   = smf;
    float* KsT  = smf + NS_ * CH;
    float* sQ   = KsT + 64 * 129;

    int bh = blockIdx.x, ch = blockIdx.y, t = threadIdx.x;
    int lane = t & 31, w = t >> 5;
    int l0 = ch * CH;

    for (int f = t; f < NS_ * 16; f += 256) {
        int u = f >> 4, d4 = f & 15;
        int l = g_topidx[bh * NS_ + u];
        *(float4*)&sQ[u * 64 + d4 * 4] =
            *(const float4*)(g_Q + ((size_t)bh * L_ + l) * D_ + d4 * 4);
    }

    const int ubeg = (t >> 7) ? 14 : 0;
    const int ucnt = (t >> 7) ? 13 : 14;
    const int kk = t & 127;
#pragma unroll 1
    for (int st = 0; st < CH / 128; st++) {
        __syncthreads();
        for (int f = t; f < 128 * 16; f += 256) {
            int kr = f >> 4, d4 = f & 15;
            float4 v = *(const float4*)(g_K + ((size_t)bh * L_ + l0 + st * 128 + kr) * D_ + d4 * 4);
            KsT[(d4*4+0) * 129 + kr] = v.x; KsT[(d4*4+1) * 129 + kr] = v.y;
            KsT[(d4*4+2) * 129 + kr] = v.z; KsT[(d4*4+3) * 129 + kr] = v.w;
        }
        __syncthreads();
        float acc[14];
#pragma unroll
        for (int i = 0; i < 14; i++) acc[i] = 0.f;
#pragma unroll
        for (int d0 = 0; d0 < 64; d0 += 4) {
            float k0 = KsT[d0*129 + kk], k1 = KsT[(d0+1)*129 + kk];
            float k2 = KsT[(d0+2)*129 + kk], k3 = KsT[(d0+3)*129 + kk];
#pragma unroll
            for (int i = 0; i < 14; i++) {
                if (i < ucnt) {
                    float4 q = *(const float4*)&sQ[(ubeg + i) * 64 + d0];
                    acc[i] += q.x*k0 + q.y*k1 + q.z*k2 + q.w*k3;
                }
            }
        }
#pragma unroll
        for (int i = 0; i < 14; i++)
            if (i < ucnt) sS[(ubeg + i) * CH + st * 128 + kk] = acc[i] * 0.125f;
    }
    __syncthreads();

    for (int u = w; u < NS_; u += 8) {
        float mx = -__int_as_float(0x7f800000);
#pragma unroll
        for (int j = 0; j < CH / 32; j++)
            mx = fmaxf(mx, sS[u * CH + lane + j * 32]);
#pragma unroll
        for (int off = 16; off > 0; off >>= 1)
            mx = fmaxf(mx, __shfl_xor_sync(0xffffffffu, mx, off));
        float ss = 0.f;
#pragma unroll
        for (int j = 0; j < CH / 32; j++) {
            float e = __expf(sS[u * CH + lane + j * 32] - mx);
            sS[u * CH + lane + j * 32] = e;
            ss += e;
        }
#pragma unroll
        for (int off = 16; off > 0; off >>= 1)
            ss += __shfl_xor_sync(0xffffffffu, ss, off);
        if (lane == 0) {
            int pi = (bh * NCH + ch) * NS_ + u;
            g_attM[pi] = mx;
            g_attS[pi] = ss;
        }
    }
    __syncthreads();

    int d = t & 63, ug = t >> 6;
    float acc[7];
#pragma unroll
    for (int j = 0; j < 7; j++) acc[j] = 0.f;
    for (int k = 0; k < CH; k += 4) {
        float v0 = g_V[((size_t)bh * L_ + l0 + k + 0) * D_ + d];
        float v1 = g_V[((size_t)bh * L_ + l0 + k + 1) * D_ + d];
        float v2 = g_V[((size_t)bh * L_ + l0 + k + 2) * D_ + d];
        float v3 = g_V[((size_t)bh * L_ + l0 + k + 3) * D_ + d];
#pragma unroll
        for (int j = 0; j < 7; j++) {
            int u = ug + j * 4;
            if (u < NS_) {
                float4 p = *(const float4*)&sS[u * CH + k];
                acc[j] += p.x*v0 + p.y*v1 + p.z*v2 + p.w*v3;
            }
        }
    }
#pragma unroll
    for (int j = 0; j < 7; j++) {
        int u = ug + j * 4;
        if (u < NS_)
            g_attO[((size_t)(bh * NCH + ch) * NS_ + u) * D_ + d] = acc[j];
    }
}

// ---------------- layer-1 attention over low-rank K1/V1 ----------------
__global__ __launch_bounds__(256)
void att1_fused_kernel() {
    __shared__ float sQ[64];
    __shared__ float sS[SLOTS];
    __shared__ float red[256];
    __shared__ float sstat[2];
    int bu = blockIdx.x;
    int bh = bu / NS_, u = bu % NS_;
    int b = bh >> 3, h = bh & 7;
    int t = threadIdx.x;
    int cnt = g_cnt[b];
    int lsel = g_topidx[bh * NS_ + u];
    if (t < 64) sQ[t] = g_Q1[((size_t)bh * L_ + lsel) * D_ + t];
    __syncthreads();

    if (t < 32) {
        float p = sQ[t] * g_basekv[(size_t)b * DM_ + h * D_ + t]
                + sQ[t + 32] * g_basekv[(size_t)b * DM_ + h * D_ + t + 32];
#pragma unroll
        for (int off = 16; off > 0; off >>= 1)
            p += __shfl_xor_sync(0xffffffffu, p, off);
        if (t == 0) sstat[0] = 0.125f * p;
    }
    __syncthreads();
    float qb = sstat[0];

    float sj = -__int_as_float(0x7f800000);
    if (t < cnt) {
        const float4* c = (const float4*)(g_ck + ((size_t)(b * SLOTS + t)) * DM_ + h * D_);
        float dot = 0.f;
#pragma unroll
        for (int d4 = 0; d4 < 16; d4++) {
            float4 cv = c[d4];
            dot += sQ[d4*4]*cv.x + sQ[d4*4+1]*cv.y + sQ[d4*4+2]*cv.z + sQ[d4*4+3]*cv.w;
        }
        sj = qb + 0.125f * dot;
        sS[t] = sj;
    }
    red[t] = sj;
    __syncthreads();
    for (int s = 128; s > 0; s >>= 1) {
        if (t < s) red[t] = fmaxf(red[t], red[t + s]);
        __syncthreads();
    }
    float m = fmaxf(red[0], qb);
    __syncthreads();

    float e = 0.f;
    if (t < cnt) { e = __expf(sS[t] - m); sS[t] = e; }
    red[t] = e;
    __syncthreads();
    for (int s = 128; s > 0; s >>= 1) {
        if (t < s) red[t] += red[t + s];
        __syncthreads();
    }
    if (t == 0)
        sstat[1] = 1.f / (red[0] + (float)(L_ - cnt) * __expf(qb - m));
    __syncthreads();
    float inv = sstat[1];

    if (t < 64) {
        float o = 0.f;
        for (int j = 0; j < cnt; j++)
            o += sS[j] * g_ck[CKOFF + ((size_t)(b * SLOTS + j)) * DM_ + h * D_ + t];
        o = o * inv + g_basekv[(size_t)(B_ + b) * DM_ + h * D_ + t];
        g_outtop[(bh * NS_ + u) * D_ + t] = o;
    }
}

// ---------------- slot assignment ----------------
__global__ __launch_bounds__(256)
void slot_assign_kernel() {
    int b = blockIdx.x, t = threadIdx.x;
    __shared__ int cs[256];
    int base = t * 16;
    int c = 0;
#pragma unroll
    for (int i = 0; i < 16; i++)
        if (g_map[b * L_ + base + i] == 1) c++;
    cs[t] = c;
    __syncthreads();
    for (int off = 1; off < 256; off <<= 1) {
        int v = (t >= off) ? cs[t - off] : 0;
        __syncthreads();
        cs[t] += v;
        __syncthreads();
    }
    int slot = cs[t] - c;
#pragma unroll
    for (int i = 0; i < 16; i++) {
        if (g_map[b * L_ + base + i] == 1)
            g_map[b * L_ + base + i] = slot++;
    }
    if (t == 255) g_cnt[b] = cs[255];
}

__global__ __launch_bounds__(128)
void corr_compact_kernel() {
    int blk = blockIdx.x, z = blockIdx.y;
    int bh0 = blk / NS_, u = blk % NS_;
    int b = bh0 >> 3, h0 = bh0 & 7;
    int t = threadIdx.x;
    __shared__ float qv[64];
    if (t < 64) qv[t] = g_outtop[(bh0 * NS_ + u) * 64 + t] - g_meanV[bh0 * 64 + t];
    __syncthreads();
    const float* T = g_Tkv + (size_t)z * DM_ * DM_;
    int l = g_topidx[bh0 * NS_ + u];
    int slot = g_map[b * L_ + l];
    float a0 = 0.f, a1 = 0.f, a2 = 0.f, a3 = 0.f;
#pragma unroll 8
    for (int k = 0; k < 64; k++) {
        float q = qv[k];
        float4 wv = *(const float4*)(T + (size_t)(h0 * 64 + k) * DM_ + t * 4);
        a0 += q * wv.x; a1 += q * wv.y; a2 += q * wv.z; a3 += q * wv.w;
    }
    float* dst = g_ck + (size_t)z * CKOFF + ((size_t)(b * SLOTS + slot)) * DM_ + t * 4;
    atomicAdd(dst + 0, a0); atomicAdd(dst + 1, a1);
    atomicAdd(dst + 2, a2); atomicAdd(dst + 3, a3);
}

// ---------------- generic GEMV: partials then combine ----------------
__global__ __launch_bounds__(512)
void base1g_kernel(const float* __restrict__ invec, const float* __restrict__ w) {
    int b = blockIdx.x, kc = blockIdx.y, n = threadIdx.x;
    __shared__ float mc[64];
    if (n < 64) mc[n] = invec[b * DM_ + kc * 64 + n];
    __syncthreads();
    float s = 0.f;
#pragma unroll 8
    for (int k = 0; k < 64; k++) s += mc[k] * w[(size_t)(kc * 64 + k) * DM_ + n];
    g_basep[(b * 8 + kc) * DM_ + n] = s;
}

__global__ __launch_bounds__(512)
void base2g_kernel(const float* __restrict__ bias, float* __restrict__ outv) {
    int b = blockIdx.x, n = threadIdx.x;
    float s = bias[n];
#pragma unroll
    for (int p = 0; p < 8; p++) s += g_basep[(b * 8 + p) * DM_ + n];
    outv[b * DM_ + n] = s;
}

struct KV2 { const float* w[2]; const float* bias[2]; };
__global__ __launch_bounds__(512)
void basekv1_kernel(const float* __restrict__ invec, KV2 kv) {
    int b = blockIdx.x, kc = blockIdx.y, z = blockIdx.z, n = threadIdx.x;
    __shared__ float mc[64];
    if (n < 64) mc[n] = invec[b * DM_ + kc * 64 + n];
    __syncthreads();
    const float* w = kv.w[z];
    float s = 0.f;
#pragma unroll 8
    for (int k = 0; k < 64; k++) s += mc[k] * w[(size_t)(kc * 64 + k) * DM_ + n];
    g_basep2[((z * B_ + b) * 8 + kc) * DM_ + n] = s;
}

__global__ __launch_bounds__(512)
void basekv2_kernel(KV2 kv) {
    int b = blockIdx.x, z = blockIdx.y, n = threadIdx.x;
    float s = kv.bias[z][n];
#pragma unroll
    for (int p = 0; p < 8; p++) s += g_basep2[((z * B_ + b) * 8 + p) * DM_ + n];
    g_basekv[(z * B_ + b) * DM_ + n] = s;
}

// ---------------- output broadcasts ----------------
__global__ __launch_bounds__(256)
void bcast_out_kernel(const float* __restrict__ xs, float* __restrict__ out,
                      const float* __restrict__ basev, int row_off) {
    int i4 = blockIdx.x * 256 + threadIdx.x;
    int n4 = i4 & 127;
    int l = (i4 >> 7) & 4095;
    int b = i4 / (L_ * 128);
    size_t oi = ((size_t)(b * 8192 + row_off + l)) * 128 + n4;
    float4 a = ((const float4*)xs)[oi];
    float4 s = ((const float4*)basev)[b * 128 + n4];
    a.x += s.x; a.y += s.y; a.z += s.z; a.w += s.w;
    ((float4*)out)[oi] = a;
}

__global__ __launch_bounds__(128)
void corr_kernel(const float* __restrict__ wo, float* __restrict__ dst, int row_off) {
    int blk = blockIdx.x;
    int bh = blk / NS_, u = blk % NS_;
    int b = bh >> 3, h = bh & 7;
    int t = threadIdx.x;
    __shared__ float qv[64];
    if (t < 64) qv[t] = g_outtop[(bh * NS_ + u) * 64 + t] - g_meanV[bh * 64 + t];
    __syncthreads();
    int l = g_topidx[bh * NS_ + u];
    float a0 = 0.f, a1 = 0.f, a2 = 0.f, a3 = 0.f;
#pragma unroll 8
    for (int k = 0; k < 64; k++) {
        float q = qv[k];
        float4 wv = *(const float4*)(wo + (size_t)(h * 64 + k) * DM_ + t * 4);
        a0 += q * wv.x; a1 += q * wv.y; a2 += q * wv.z; a3 += q * wv.w;
    }
    float* d = dst + ((size_t)(b * 8192 + row_off + l)) * DM_ + t * 4;
    atomicAdd(d + 0, a0); atomicAdd(d + 1, a1);
    atomicAdd(d + 2, a2); atomicAdd(d + 3, a3);
}

// ---------------- host orchestration ----------------
extern "C" void kernel_launch(void* const* d_in, const int* in_sizes, int n_in,
                              void* d_out, int out_size) {
    const float* xs  = (const float*)d_in[0];
    const float* xd  = (const float*)d_in[1];
    const float* xp  = (const float*)d_in[2];
    const float* w0q = (const float*)d_in[3];
    const float* w0k = (const float*)d_in[4];
    const float* w0v = (const float*)d_in[5];
    const float* w0o = (const float*)d_in[6];
    const float* b0q = (const float*)d_in[7];
    const float* b0k = (const float*)d_in[8];
    const float* b0v = (const float*)d_in[9];
    const float* b0o = (const float*)d_in[10];
    const float* w1q = (const float*)d_in[11];
    const float* w1k = (const float*)d_in[12];
    const float* w1v = (const float*)d_in[13];
    const float* w1o = (const float*)d_in[14];
    const float* b1q = (const float*)d_in[15];
    const float* b1k = (const float*)d_in[16];
    const float* b1v = (const float*)d_in[17];
    const float* b1o = (const float*)d_in[18];
    float* out = (float*)d_out;

    float *pQ, *pQ1, *pK, *pV, *pmv, *pb0, *pb1, *pck, *pTkv;
    int *pidxA, *pidxB, *pmap;
    __nv_bfloat16 *pAxdH, *pAxdL, *pAxpH, *pAxpL, *pWtH, *pWtL;
    cudaGetSymbolAddress((void**)&pQ, g_Q);
    cudaGetSymbolAddress((void**)&pQ1, g_Q1);
    cudaGetSymbolAddress((void**)&pK, g_K);
    cudaGetSymbolAddress((void**)&pV, g_V);
    cudaGetSymbolAddress((void**)&pmv, g_meanV);
    cudaGetSymbolAddress((void**)&pb0, g_base0);
    cudaGetSymbolAddress((void**)&pb1, g_base1);
    cudaGetSymbolAddress((void**)&pck, g_ck);
    cudaGetSymbolAddress((void**)&pTkv, g_Tkv);
    cudaGetSymbolAddress((void**)&pmap, g_map);
    cudaGetSymbolAddress((void**)&pidxA, g_idxA);
    cudaGetSymbolAddress((void**)&pidxB, g_idxB);
    cudaGetSymbolAddress((void**)&pAxdH, g_Axd_hi);
    cudaGetSymbolAddress((void**)&pAxdL, g_Axd_lo);
    cudaGetSymbolAddress((void**)&pAxpH, g_Axp_hi);
    cudaGetSymbolAddress((void**)&pAxpL, g_Axp_lo);
    cudaGetSymbolAddress((void**)&pWtH, g_Wt_hi);
    cudaGetSymbolAddress((void**)&pWtL, g_Wt_lo);

    cudaFuncSetAttribute(gemm_mma4, cudaFuncAttributeMaxDynamicSharedMemorySize, GSMEM);
    cudaFuncSetAttribute(att_fused_kernel, cudaFuncAttributeMaxDynamicSharedMemorySize, ATT_SMEM);

    // scratch init
    cudaMemsetAsync(pmap, 0xFF, (size_t)B_ * L_ * sizeof(int));
    cudaMemsetAsync(pck, 0, (size_t)2 * B_ * SLOTS * DM_ * sizeof(float));
    cudaMemsetAsync(pTkv, 0, (size_t)2 * DM_ * DM_ * sizeof(float));

    // idx tables
    {
        unsigned a42, b42, a43, b43;
        tf2x32(0u, 42u, 0u, 1u, &a42, &b42);
        tf2x32(0u, 43u, 0u, 1u, &a43, &b43);
        IdxKeys ik;
        ik.k0[0] = a42; ik.k1[0] = b42; ik.out[0] = pidxA;
        ik.k0[1] = a43; ik.k1[1] = b43; ik.out[1] = pidxB;
        idx2_kernel<<<dim3((L_ * NS_ + 255) / 256, 2), 256>>>(ik);
    }

    W4 ws;
    ws.w[0] = w0q; ws.w[1] = w0k; ws.w[2] = w0v; ws.w[3] = w1q;
    wt_cvt_all_kernel<<<dim3(16, 16, 4), dim3(32, 32)>>>(ws, pWtH, pWtL);

    // T = Wo0 @ W1{k,v}: split-K with direct atomic accumulation
    TW tw; tw.b[0] = w1k; tw.b[1] = w1v;
    sgemm_T_part<<<dim3(8, 8, 32), 256>>>(w0o, tw);

    const int N4 = BL_ * DM_ / 4;     // 2097152
    const int N4Q = N4 / 4;           // 524288
    {
        Cvt2 c;
        c.src[0] = (const float4*)xd; c.src[1] = (const float4*)xp;
        c.hi[0] = (__nv_bfloat162*)pAxdH; c.hi[1] = (__nv_bfloat162*)pAxpH;
        c.lo[0] = (__nv_bfloat162*)pAxdL; c.lo[1] = (__nv_bfloat162*)pAxpL;
        cvt_pair2_kernel<<<dim3(N4Q / 256, 2), 256>>>(c, N4Q);
    }

    // ---- ALL 4 dense GEMMs in one launch (Q0, K0, V0, Q1) ----
    {
        G4 g4;
        size_t WS = (size_t)DM_ * DM_;
        g4.j[0].ahi = pAxpH; g4.j[0].alo = pAxpL; g4.j[0].bhi = pWtH + 0*WS; g4.j[0].blo = pWtL + 0*WS; g4.j[0].bias = b0q; g4.j[0].c = pQ;
        g4.j[1].ahi = pAxdH; g4.j[1].alo = pAxdL; g4.j[1].bhi = pWtH + 1*WS; g4.j[1].blo = pWtL + 1*WS; g4.j[1].bias = b0k; g4.j[1].c = pK;
        g4.j[2].ahi = pAxdH; g4.j[2].alo = pAxdL; g4.j[2].bhi = pWtH + 2*WS; g4.j[2].blo = pWtL + 2*WS; g4.j[2].bias = b0v; g4.j[2].c = pV;
        g4.j[3].ahi = pAxdH; g4.j[3].alo = pAxdL; g4.j[3].bhi = pWtH + 3*WS; g4.j[3].blo = pWtL + 3*WS; g4.j[3].bias = b1q; g4.j[3].c = pQ1;
        gemm_mma4<<<dim3(DM_ / 128, BL_ / 128, 4), 256, GSMEM>>>(g4);
    }

    // ---- layer 0 attention ----
    sample_m_kernel<<<(BH_ * L_) / 8, 256>>>(pidxA);
    topk_kernel<<<BH_, 256>>>(1);         // also marks g_map
    meanv1_kernel<<<dim3(BH_, 16), 256>>>();
    att_fused_kernel<<<dim3(BH_, NCH), 256, ATT_SMEM>>>();
    combine2_kernel<<<BH_ * NS_ + BH_, 64>>>();   // att_combine + meanv2

    // base0 = meanctx0 @ Wo0 + bo0
    base1g_kernel<<<dim3(B_, 8), 512>>>(pmv, w0o);
    base2g_kernel<<<B_, 512>>>(b0o, pb0);

    // output upper half (xp2)
    bcast_out_kernel<<<(B_ * L_ * 128) / 256, 256>>>(xs, out, pb0, 4096);
    corr_kernel<<<BH_ * NS_, 128>>>(w0o, out, 4096);

    // ---- compact low-rank K1/V1 ----
    slot_assign_kernel<<<B_, 256>>>();
    corr_compact_kernel<<<dim3(BH_ * NS_, 2), 128>>>();
    {
        KV2 kv;
        kv.w[0] = w1k; kv.w[1] = w1v;
        kv.bias[0] = b1k; kv.bias[1] = b1v;
        basekv1_kernel<<<dim3(B_, 8, 2), 512>>>(pb0, kv);
        basekv2_kernel<<<dim3(B_, 2), 512>>>(kv);
    }

    // ---- layer 1 attention (low-rank K1/V1, Q from g_Q1) ----
    sample_m1_kernel<<<(BH_ * L_) / 8, 256>>>(pidxB);
    topk_kernel<<<BH_, 256>>>(0);
    meanv1b_kernel<<<BH_, 64>>>();
    att1_fused_kernel<<<BH_ * NS_, 256>>>();

    // base1 + output lower half (xd2)
    base1g_kernel<<<dim3(B_, 8), 512>>>(pmv, w1o);
    base2g_kernel<<<B_, 512>>>(b1o, pb1);
    bcast_out_kernel<<<(B_ * L_ * 128) / 256, 256>>>(xs, out, pb1, 0);
    corr_kernel<<<BH_ * NS_, 128>>>(w1o, out, 0);
}